// round 12
// baseline (speedup 1.0000x reference)
#include <cuda_runtime.h>
#include <cuda_bf16.h>
#include <cstdint>
#include <math.h>

#define B_   8
#define N_   1024
#define DM   512
#define H_   8
#define DH   64
#define QKVD 1536
#define NS_  1
#define L2E_ 1.4426950408889634f
#define SCALE_L2E (0.125f * L2E_)   // attn scale folded with log2(e)

// ---------------- scratch (device globals; no allocations) ----------------
__device__ float g_qkv[(size_t)B_ * N_ * QKVD];        //  50.3 MB  [b][n][3D]
__device__ float g_bias[(size_t)B_ * H_ * N_ * N_];    // 268.4 MB  pre-scaled by alpha*log2e
__device__ float g_att[(size_t)B_ * N_ * DM];          //  16.8 MB  [b][n][h*64+d]
// pre-split bf16 hi/lo K and V (written by qkv GEMM epilogue)
__device__ __nv_bfloat16 g_kh[(size_t)B_ * N_ * DM];
__device__ __nv_bfloat16 g_kl[(size_t)B_ * N_ * DM];
__device__ __nv_bfloat16 g_vh[(size_t)B_ * N_ * DM];
__device__ __nv_bfloat16 g_vl[(size_t)B_ * N_ * DM];

// =====================================================================
// common helpers
// =====================================================================
#define MMA16816(d, a, b) \
  asm volatile("mma.sync.aligned.m16n8k16.row.col.f32.bf16.bf16.f32 " \
    "{%0,%1,%2,%3}, {%4,%5,%6,%7}, {%8,%9}, {%0,%1,%2,%3};" \
    : "+f"((d)[0]), "+f"((d)[1]), "+f"((d)[2]), "+f"((d)[3]) \
    : "r"((a)[0]), "r"((a)[1]), "r"((a)[2]), "r"((a)[3]), \
      "r"((b)[0]), "r"((b)[1]))

#define LDMX2T(r0, r1, addr) \
  asm volatile("ldmatrix.sync.aligned.m8n8.x2.trans.shared.b16 {%0,%1}, [%2];" \
    : "=r"(r0), "=r"(r1) : "r"(addr))

__device__ __forceinline__ void split2(float a, float b, uint32_t& hi, uint32_t& lo)
{
    __nv_bfloat16 ha = __float2bfloat16(a), hb = __float2bfloat16(b);
    __nv_bfloat16 la = __float2bfloat16(a - __bfloat162float(ha));
    __nv_bfloat16 lb = __float2bfloat16(b - __bfloat162float(hb));
    __nv_bfloat162 h{ha, hb}, l{la, lb};
    hi = *(uint32_t*)&h; lo = *(uint32_t*)&l;
}

__device__ __forceinline__ void split_store(__nv_bfloat16* hp, __nv_bfloat16* lp,
                                            float4 v)
{
    uint32_t h0, l0, h1, l1;
    split2(v.x, v.y, h0, l0);
    split2(v.z, v.w, h1, l1);
    *(uint2*)hp = make_uint2(h0, h1);
    *(uint2*)lp = make_uint2(l0, l1);
}

// single-MUFU exp2 (softmax runs in base-2 domain)
__device__ __forceinline__ float ex2f(float x)
{
    float r;
    asm("ex2.approx.f32 %0, %1;" : "=f"(r) : "f"(x));
    return r;
}

// tanh-form GELU, single MUFU (tanh.approx): 4 FMA-class + 1 MUFU.
__device__ __forceinline__ float gelu_tanh(float t)
{
    float t2 = t * t;
    float u  = fmaf(0.0356774081f, t2, 0.7978845608f);
    float z  = t * u;
    float th;
    asm("tanh.approx.f32 %0, %1;" : "=f"(th) : "f"(z));
    float ht = 0.5f * t;
    return fmaf(ht, th, ht);
}

// =====================================================================
// mma.sync bf16 GEMM body (R5-proven). split_kv: qkv epilogue also emits
// pre-split bf16 hi/lo K and V planes (CTA-uniform branch; 128-col tiles
// never straddle the Q/K/V 512-col boundaries).
// =====================================================================
#define KC    16
#define LDSB  24
#define PLANE (128 * LDSB)
#define STAGE (4 * PLANE)
#define GEMM_SMEM (2 * STAGE * 2)

__device__ __forceinline__ void gemm_mma_body(
    const float* __restrict__ A, const float* __restrict__ W,
    const float* __restrict__ bias, float* __restrict__ C,
    int Nc, int K, int m0, int n0, int split_kv)
{
    extern __shared__ __nv_bfloat16 smb[];
    const int tid  = threadIdx.x;
    const int wid  = tid >> 5, lane = tid & 31;
    const int g    = lane >> 2, tg = lane & 3;
    const int wm   = (wid >> 2) * 64,  wn = (wid & 3) * 32;

    float acc[4][4][4];
    #pragma unroll
    for (int mt = 0; mt < 4; mt++)
        #pragma unroll
        for (int nt = 0; nt < 4; nt++)
            #pragma unroll
            for (int r = 0; r < 4; r++) acc[mt][nt][r] = 0.f;

    const int NCH = K / KC;
    const int prow0 = tid >> 2;
    const int pk4   = (tid & 3) << 2;
    float4 ra[2], rw[2];

    {
        #pragma unroll
        for (int t = 0; t < 2; t++) {
            int row = prow0 + t * 64;
            ra[t] = *(const float4*)&A[(size_t)(m0 + row) * K + pk4];
            rw[t] = *(const float4*)&W[(size_t)(n0 + row) * K + pk4];
        }
        __nv_bfloat16* s = smb;
        #pragma unroll
        for (int t = 0; t < 2; t++) {
            int row = prow0 + t * 64;
            int off = row * LDSB + pk4;
            split_store(s + off,             s + PLANE + off,     ra[t]);
            split_store(s + 2 * PLANE + off, s + 3 * PLANE + off, rw[t]);
        }
    }

    for (int c = 0; c < NCH; c++) {
        __syncthreads();

        if (c + 1 < NCH) {
            const int k0 = (c + 1) * KC;
            #pragma unroll
            for (int t = 0; t < 2; t++) {
                int row = prow0 + t * 64;
                ra[t] = *(const float4*)&A[(size_t)(m0 + row) * K + k0 + pk4];
                rw[t] = *(const float4*)&W[(size_t)(n0 + row) * K + k0 + pk4];
            }
        }

        {
            const __nv_bfloat16* Ah = smb + (c & 1) * STAGE;
            const __nv_bfloat16* Al = Ah + PLANE;
            const __nv_bfloat16* Bh = Ah + 2 * PLANE;
            const __nv_bfloat16* Bl = Ah + 3 * PLANE;

            uint32_t ah[4][4], al[4][4], bh[4][2], bl[4][2];
            #pragma unroll
            for (int mt = 0; mt < 4; mt++) {
                int base = (wm + mt * 16 + g) * LDSB + tg * 2;
                ah[mt][0] = *(const uint32_t*)(Ah + base);
                ah[mt][1] = *(const uint32_t*)(Ah + base + 8 * LDSB);
                ah[mt][2] = *(const uint32_t*)(Ah + base + 8);
                ah[mt][3] = *(const uint32_t*)(Ah + base + 8 * LDSB + 8);
                al[mt][0] = *(const uint32_t*)(Al + base);
                al[mt][1] = *(const uint32_t*)(Al + base + 8 * LDSB);
                al[mt][2] = *(const uint32_t*)(Al + base + 8);
                al[mt][3] = *(const uint32_t*)(Al + base + 8 * LDSB + 8);
            }
            #pragma unroll
            for (int nt = 0; nt < 4; nt++) {
                int base = (wn + nt * 8 + g) * LDSB + tg * 2;
                bh[nt][0] = *(const uint32_t*)(Bh + base);
                bh[nt][1] = *(const uint32_t*)(Bh + base + 8);
                bl[nt][0] = *(const uint32_t*)(Bl + base);
                bl[nt][1] = *(const uint32_t*)(Bl + base + 8);
            }
            #pragma unroll
            for (int mt = 0; mt < 4; mt++)
                #pragma unroll
                for (int nt = 0; nt < 4; nt++)
                    MMA16816(acc[mt][nt], ah[mt], bh[nt]);
            #pragma unroll
            for (int mt = 0; mt < 4; mt++)
                #pragma unroll
                for (int nt = 0; nt < 4; nt++)
                    MMA16816(acc[mt][nt], al[mt], bh[nt]);
            #pragma unroll
            for (int mt = 0; mt < 4; mt++)
                #pragma unroll
                for (int nt = 0; nt < 4; nt++)
                    MMA16816(acc[mt][nt], ah[mt], bl[nt]);
        }

        if (c + 1 < NCH) {
            __nv_bfloat16* s = smb + ((c + 1) & 1) * STAGE;
            #pragma unroll
            for (int t = 0; t < 2; t++) {
                int row = prow0 + t * 64;
                int off = row * LDSB + pk4;
                split_store(s + off,             s + PLANE + off,     ra[t]);
                split_store(s + 2 * PLANE + off, s + 3 * PLANE + off, rw[t]);
            }
        }
    }

    const int is_k = split_kv && (n0 >= DM) && (n0 < 2 * DM);
    const int is_v = split_kv && (n0 >= 2 * DM);
    __nv_bfloat16* dsth = is_v ? g_vh : g_kh;
    __nv_bfloat16* dstl = is_v ? g_vl : g_kl;
    const int cb0 = n0 - (is_v ? 2 * DM : DM);

    #pragma unroll
    for (int mt = 0; mt < 4; mt++) {
        #pragma unroll
        for (int nt = 0; nt < 4; nt++) {
            int row = m0 + wm + mt * 16 + g;
            int col = n0 + wn + nt * 8 + tg * 2;
            float bx = 0.f, by = 0.f;
            if (bias) { bx = bias[col]; by = bias[col + 1]; }
            *(float2*)&C[(size_t)row * Nc + col] =
                make_float2(acc[mt][nt][0] + bx, acc[mt][nt][1] + by);
            *(float2*)&C[(size_t)(row + 8) * Nc + col] =
                make_float2(acc[mt][nt][2] + bx, acc[mt][nt][3] + by);

            if (is_k || is_v) {
                size_t kidx = (size_t)row * DM + (cb0 + wn + nt * 8 + tg * 2);
                uint32_t hh, ll;
                split2(acc[mt][nt][0], acc[mt][nt][1], hh, ll);
                *(uint32_t*)&dsth[kidx] = hh;
                *(uint32_t*)&dstl[kidx] = ll;
                split2(acc[mt][nt][2], acc[mt][nt][3], hh, ll);
                *(uint32_t*)&dsth[kidx + 8 * DM] = hh;
                *(uint32_t*)&dstl[kidx + 8 * DM] = ll;
            }
        }
    }
}

__global__ void __launch_bounds__(256, 2)
k_gemm_qkv_mma(const float* __restrict__ x, const float* __restrict__ qkv_w)
{
    gemm_mma_body(x, qkv_w, nullptr, g_qkv, QKVD, DM,
                  blockIdx.y * 128, blockIdx.x * 128, 1);
}

__global__ void __launch_bounds__(256, 2)
k_gemm_out_mma(const float* __restrict__ out_w, const float* __restrict__ out_b,
               float* __restrict__ out)
{
    gemm_mma_body(g_att, out_w, out_b, out, DM, DM,
                  blockIdx.y * 128, blockIdx.x * 128, 0);
}

// =====================================================================
// Pairwise bias MLP — tensorized (R8-proven). Bias stored pre-scaled
// by alpha*log2(e) for the base-2 softmax.
// =====================================================================
__global__ void __launch_bounds__(256)
k_bias_mma(const float* __restrict__ coords, const float* __restrict__ cs,
           const float* __restrict__ w1, const float* __restrict__ b1,
           const float* __restrict__ w2, const float* __restrict__ b2,
           const float* __restrict__ alpha_p)
{
    __shared__ float sj[128 * 3];
    __shared__ float sci[8 * 3];
    __shared__ float sw1[128];
    __shared__ float sb1[32];
    __shared__ float sw2[256];
    __shared__ float sb2[8];
    __shared__ float sinv[3];
    __shared__ float salpha;

    const int tid = threadIdx.x;
    const int w = tid >> 5, lane = tid & 31;
    const int g = lane >> 2, tg = lane & 3;
    const int b = blockIdx.z;
    const int j0 = blockIdx.x * 128;
    const int i0 = blockIdx.y * 8;

    if (tid < 3) sinv[tid] = 1.0f / cs[tid];
    if (tid < 128) sw1[tid] = w1[tid];
    if (tid >= 128 && tid < 160) sb1[tid - 128] = b1[tid - 128];
    if (tid >= 160 && tid < 168) sb2[tid - 160] = b2[tid - 160];
    if (tid == 168) salpha = alpha_p[0] * L2E_;
    __syncthreads();
    for (int idx = tid; idx < 384; idx += 256) {
        int r = idx / 3, c = idx - r * 3;
        sj[idx] = coords[((size_t)(b * N_ + j0 + r)) * 3 + c] * sinv[c];
    }
    if (tid < 24) {
        int r = tid / 3, c = tid - r * 3;
        sci[tid] = coords[((size_t)(b * N_ + i0 + r)) * 3 + c] * sinv[c];
    }
    if (tid < 256) sw2[tid] = w2[tid];
    __syncthreads();

    uint32_t bw1h[4][2], bw1l[4][2];
    #pragma unroll
    for (int nt = 0; nt < 4; nt++) {
        float x0 = 0.f, x1 = 0.f;
        if (tg < 2) {
            x0 = sw1[(nt * 8 + g) * 4 + 2 * tg];
            x1 = sw1[(nt * 8 + g) * 4 + 2 * tg + 1];
        }
        split2(x0, x1, bw1h[nt][0], bw1l[nt][0]);
        bw1h[nt][1] = 0u; bw1l[nt][1] = 0u;
    }
    uint32_t bw2h[2][2], bw2l[2][2];
    #pragma unroll
    for (int kc = 0; kc < 2; kc++) {
        split2(sw2[g * 32 + 16 * kc + 2 * tg],
               sw2[g * 32 + 16 * kc + 2 * tg + 1], bw2h[kc][0], bw2l[kc][0]);
        split2(sw2[g * 32 + 16 * kc + 2 * tg + 8],
               sw2[g * 32 + 16 * kc + 2 * tg + 9], bw2h[kc][1], bw2l[kc][1]);
    }

    const int jlA = w * 16 + g;
    const int jlB = jlA + 8;
    const float cjAx = sj[jlA * 3], cjAy = sj[jlA * 3 + 1], cjAz = sj[jlA * 3 + 2];
    const float cjBx = sj[jlB * 3], cjBy = sj[jlB * 3 + 1], cjBz = sj[jlB * 3 + 2];
    const int jA = j0 + jlA, jB = j0 + jlB;
    const int h0 = 2 * tg, h1 = h0 + 1;
    const float bh0 = sb2[h0], bh1 = sb2[h1];

    #pragma unroll
    for (int ii = 0; ii < 8; ii++) {
        const int i = i0 + ii;
        const float cix = sci[ii * 3], ciy = sci[ii * 3 + 1], ciz = sci[ii * 3 + 2];

        float dxA = cix - cjAx, dyA = ciy - cjAy, dzA = ciz - cjAz;
        float dsA = sqrtf(fmaf(dxA, dxA, fmaf(dyA, dyA, dzA * dzA)));
        float dxB = cix - cjBx, dyB = ciy - cjBy, dzB = ciz - cjBz;
        float dsB = sqrtf(fmaf(dxB, dxB, fmaf(dyB, dyB, dzB * dzB)));

        float vA0 = tg == 0 ? dxA : (tg == 1 ? dzA : 0.f);
        float vA1 = tg == 0 ? dyA : (tg == 1 ? dsA : 0.f);
        float vB0 = tg == 0 ? dxB : (tg == 1 ? dzB : 0.f);
        float vB1 = tg == 0 ? dyB : (tg == 1 ? dsB : 0.f);
        uint32_t afh[4], afl[4];
        split2(vA0, vA1, afh[0], afl[0]);
        split2(vB0, vB1, afh[1], afl[1]);
        afh[2] = afh[3] = afl[2] = afl[3] = 0u;

        float d1[4][4];
        #pragma unroll
        for (int nt = 0; nt < 4; nt++) {
            d1[nt][0] = d1[nt][1] = d1[nt][2] = d1[nt][3] = 0.f;
            MMA16816(d1[nt], afh, bw1h[nt]);
            MMA16816(d1[nt], afl, bw1h[nt]);
            MMA16816(d1[nt], afh, bw1l[nt]);
        }

        float gv[4][4];
        #pragma unroll
        for (int nt = 0; nt < 4; nt++) {
            float ba = sb1[8 * nt + 2 * tg], bb = sb1[8 * nt + 2 * tg + 1];
            gv[nt][0] = gelu_tanh(d1[nt][0] + ba);
            gv[nt][1] = gelu_tanh(d1[nt][1] + bb);
            gv[nt][2] = gelu_tanh(d1[nt][2] + ba);
            gv[nt][3] = gelu_tanh(d1[nt][3] + bb);
        }

        float d2[4] = {0.f, 0.f, 0.f, 0.f};
        #pragma unroll
        for (int kc = 0; kc < 2; kc++) {
            uint32_t a2h[4], a2l[4];
            split2(gv[2 * kc][0],     gv[2 * kc][1],     a2h[0], a2l[0]);
            split2(gv[2 * kc][2],     gv[2 * kc][3],     a2h[1], a2l[1]);
            split2(gv[2 * kc + 1][0], gv[2 * kc + 1][1], a2h[2], a2l[2]);
            split2(gv[2 * kc + 1][2], gv[2 * kc + 1][3], a2h[3], a2l[3]);
            MMA16816(d2, a2h, bw2h[kc]);
            MMA16816(d2, a2l, bw2h[kc]);
            MMA16816(d2, a2h, bw2l[kc]);
        }

        float si = (i >= NS_) ? salpha : 0.f;
        float sA = (jA >= NS_) ? si : 0.f;
        float sB = si;
        size_t r0 = ((size_t)(b * H_ + h0) * N_ + i) * N_;
        size_t r1 = ((size_t)(b * H_ + h1) * N_ + i) * N_;
        g_bias[r0 + jA] = sA * (d2[0] + bh0);
        g_bias[r1 + jA] = sA * (d2[1] + bh1);
        g_bias[r0 + jB] = sB * (d2[2] + bh0);
        g_bias[r1 + jB] = sB * (d2[3] + bh1);
    }
}

// =====================================================================
// Tensor-core flash attention — base-2 softmax, 2 CTAs/SM, bias
// prefetch; K/V now loaded PRE-SPLIT (bf16 hi/lo) straight from global
// (converted once in the qkv GEMM epilogue) — no per-CTA cvt math.
// =====================================================================
#define LQ 72
#define ATTN_SMEM2 (36864 * 2 + 64 * 4)

__global__ void __launch_bounds__(256, 2)
k_attn_mma(const unsigned char* __restrict__ mask)
{
    extern __shared__ __nv_bfloat16 sma[];
    __nv_bfloat16* Qh = sma;
    __nv_bfloat16* Ql = sma + 9216;
    __nv_bfloat16* Kh = sma + 18432;
    __nv_bfloat16* Kl = sma + 23040;
    __nv_bfloat16* Vh = sma + 27648;
    __nv_bfloat16* Vl = sma + 32256;
    float* madd = (float*)(sma + 36864);

    const int b = blockIdx.z, h = blockIdx.y;
    const int i0 = blockIdx.x * 128;
    const int tid = threadIdx.x;
    const int w = tid >> 5, lane = tid & 31;
    const int g = lane >> 2, tg = lane & 3;

    const uint32_t vh_u32 = (uint32_t)__cvta_generic_to_shared(Vh);
    const uint32_t vl_u32 = (uint32_t)__cvta_generic_to_shared(Vl);

    #pragma unroll
    for (int t = 0; t < 8; t++) {
        int f = tid + t * 256;
        int row = f >> 4;
        int c4 = (f & 15) << 2;
        float4 v = *(const float4*)&g_qkv[((size_t)(b * N_ + i0 + row)) * QKVD + h * DH + c4];
        split_store(Qh + row * LQ + c4, Ql + row * LQ + c4, v);
    }

    float oacc[8][4];
    #pragma unroll
    for (int nt = 0; nt < 8; nt++)
        #pragma unroll
        for (int r = 0; r < 4; r++) oacc[nt][r] = 0.f;
    float m0r = -INFINITY, m1r = -INFINITY, l0r = 0.f, l1r = 0.f;

    const size_t bias_row0 = ((size_t)(b * H_ + h) * N_ + (i0 + w * 16 + g)) * N_;
    const int qrow = (w * 16 + g) * LQ + tg * 2;

    for (int j0 = 0; j0 < N_; j0 += 64) {
        __syncthreads();

        // K/V fill: straight bf16 hi/lo copies (pre-split in qkv epilogue)
        #pragma unroll
        for (int t = 0; t < 4; t++) {
            int f = tid + t * 256;
            int row = f >> 4;
            int c4 = (f & 15) << 2;
            size_t idx = ((size_t)(b * N_ + j0 + row)) * DM + h * DH + c4;
            int off = row * LQ + c4;
            *(uint2*)(Kh + off) = *(const uint2*)&g_kh[idx];
            *(uint2*)(Kl + off) = *(const uint2*)&g_kl[idx];
            *(uint2*)(Vh + off) = *(const uint2*)&g_vh[idx];
            *(uint2*)(Vl + off) = *(const uint2*)&g_vl[idx];
        }
        if (tid < 64)
            madd[tid] = mask[(size_t)b * N_ + j0 + tid] ? -1e30f : 0.0f;
        __syncthreads();

        // prefetch bias tile into registers (overlaps the S-MMA block)
        const float* bp0 = &g_bias[bias_row0 + j0];
        const float* bp1 = bp0 + 8 * N_;
        float2 bz0r[8], bz1r[8];
        #pragma unroll
        for (int nt = 0; nt < 8; nt++) {
            int col = 8 * nt + tg * 2;
            bz0r[nt] = *(const float2*)&bp0[col];
            bz1r[nt] = *(const float2*)&bp1[col];
        }

        float sacc[8][4];
        #pragma unroll
        for (int nt = 0; nt < 8; nt++)
            #pragma unroll
            for (int r = 0; r < 4; r++) sacc[nt][r] = 0.f;

        #pragma unroll
        for (int kc = 0; kc < 4; kc++) {
            int qb = qrow + kc * 16;
            uint32_t qh[4], ql[4];
            qh[0] = *(const uint32_t*)(Qh + qb);
            qh[1] = *(const uint32_t*)(Qh + qb + 8 * LQ);
            qh[2] = *(const uint32_t*)(Qh + qb + 8);
            qh[3] = *(const uint32_t*)(Qh + qb + 8 * LQ + 8);
            ql[0] = *(const uint32_t*)(Ql + qb);
            ql[1] = *(const uint32_t*)(Ql + qb + 8 * LQ);
            ql[2] = *(const uint32_t*)(Ql + qb + 8);
            ql[3] = *(const uint32_t*)(Ql + qb + 8 * LQ + 8);
            #pragma unroll
            for (int nt = 0; nt < 8; nt++) {
                int kb = (8 * nt + g) * LQ + kc * 16 + tg * 2;
                uint32_t bh[2], bl[2];
                bh[0] = *(const uint32_t*)(Kh + kb);
                bh[1] = *(const uint32_t*)(Kh + kb + 8);
                bl[0] = *(const uint32_t*)(Kl + kb);
                bl[1] = *(const uint32_t*)(Kl + kb + 8);
                MMA16816(sacc[nt], qh, bh);
                MMA16816(sacc[nt], ql, bh);
                MMA16816(sacc[nt], qh, bl);
            }
        }

        // logits (base-2): S*(scale*log2e) + prefetched bias + mask
        #pragma unroll
        for (int nt = 0; nt < 8; nt++) {
            int col = 8 * nt + tg * 2;
            float2 mz = *(float2*)&madd[col];
            sacc[nt][0] = fmaf(sacc[nt][0], SCALE_L2E, bz0r[nt].x) + mz.x;
            sacc[nt][1] = fmaf(sacc[nt][1], SCALE_L2E, bz0r[nt].y) + mz.y;
            sacc[nt][2] = fmaf(sacc[nt][2], SCALE_L2E, bz1r[nt].x) + mz.x;
            sacc[nt][3] = fmaf(sacc[nt][3], SCALE_L2E, bz1r[nt].y) + mz.y;
        }

        float mx0 = -INFINITY, mx1 = -INFINITY;
        #pragma unroll
        for (int nt = 0; nt < 8; nt++) {
            mx0 = fmaxf(mx0, fmaxf(sacc[nt][0], sacc[nt][1]));
            mx1 = fmaxf(mx1, fmaxf(sacc[nt][2], sacc[nt][3]));
        }
        mx0 = fmaxf(mx0, __shfl_xor_sync(0xffffffffu, mx0, 1));
        mx0 = fmaxf(mx0, __shfl_xor_sync(0xffffffffu, mx0, 2));
        mx1 = fmaxf(mx1, __shfl_xor_sync(0xffffffffu, mx1, 1));
        mx1 = fmaxf(mx1, __shfl_xor_sync(0xffffffffu, mx1, 2));

        float mn0 = fmaxf(m0r, mx0), mn1 = fmaxf(m1r, mx1);
        float a0 = ex2f(m0r - mn0), a1 = ex2f(m1r - mn1);
        m0r = mn0; m1r = mn1;

        float rs0 = 0.f, rs1 = 0.f;
        #pragma unroll
        for (int nt = 0; nt < 8; nt++) {
            float p0 = ex2f(sacc[nt][0] - mn0);
            float p1 = ex2f(sacc[nt][1] - mn0);
            float p2 = ex2f(sacc[nt][2] - mn1);
            float p3 = ex2f(sacc[nt][3] - mn1);
            sacc[nt][0] = p0; sacc[nt][1] = p1;
            sacc[nt][2] = p2; sacc[nt][3] = p3;
            rs0 += p0 + p1; rs1 += p2 + p3;
        }
        rs0 += __shfl_xor_sync(0xffffffffu, rs0, 1);
        rs0 += __shfl_xor_sync(0xffffffffu, rs0, 2);
        rs1 += __shfl_xor_sync(0xffffffffu, rs1, 1);
        rs1 += __shfl_xor_sync(0xffffffffu, rs1, 2);
        l0r = l0r * a0 + rs0;
        l1r = l1r * a1 + rs1;
        #pragma unroll
        for (int nt = 0; nt < 8; nt++) {
            oacc[nt][0] *= a0; oacc[nt][1] *= a0;
            oacc[nt][2] *= a1; oacc[nt][3] *= a1;
        }

        #pragma unroll
        for (int kc = 0; kc < 4; kc++) {
            uint32_t ph[4], pl[4];
            split2(sacc[2 * kc][0],     sacc[2 * kc][1],     ph[0], pl[0]);
            split2(sacc[2 * kc][2],     sacc[2 * kc][3],     ph[1], pl[1]);
            split2(sacc[2 * kc + 1][0], sacc[2 * kc + 1][1], ph[2], pl[2]);
            split2(sacc[2 * kc + 1][2], sacc[2 * kc + 1][3], ph[3], pl[3]);

            uint32_t rowoff = (uint32_t)((16 * kc + (lane & 15)) * LQ) * 2;
            #pragma unroll
            for (int ntd = 0; ntd < 8; ntd++) {
                uint32_t bh[2], bl[2];
                LDMX2T(bh[0], bh[1], vh_u32 + rowoff + ntd * 16);
                LDMX2T(bl[0], bl[1], vl_u32 + rowoff + ntd * 16);
                MMA16816(oacc[ntd], ph, bh);
                MMA16816(oacc[ntd], pl, bh);
                MMA16816(oacc[ntd], ph, bl);
            }
        }
    }

    float inv0 = 1.0f / l0r, inv1 = 1.0f / l1r;
    const size_t orow0 = ((size_t)(b * N_ + i0 + w * 16 + g)) * DM + h * DH;
    const size_t orow1 = orow0 + (size_t)8 * DM;
    #pragma unroll
    for (int nt = 0; nt < 8; nt++) {
        int col = 8 * nt + tg * 2;
        *(float2*)&g_att[orow0 + col] =
            make_float2(oacc[nt][0] * inv0, oacc[nt][1] * inv0);
        *(float2*)&g_att[orow1 + col] =
            make_float2(oacc[nt][2] * inv1, oacc[nt][3] * inv1);
    }
}

// =====================================================================
extern "C" void kernel_launch(void* const* d_in, const int* in_sizes, int n_in,
                              void* d_out, int out_size)
{
    const float* x        = (const float*)d_in[0];
    const float* coords   = (const float*)d_in[1];
    const unsigned char* mask = (const unsigned char*)d_in[2];
    const float* qkv_w    = (const float*)d_in[3];
    const float* out_w    = (const float*)d_in[4];
    const float* out_b    = (const float*)d_in[5];
    const float* alpha    = (const float*)d_in[6];
    const float* w1       = (const float*)d_in[7];
    const float* b1       = (const float*)d_in[8];
    const float* w2       = (const float*)d_in[9];
    const float* b2       = (const float*)d_in[10];
    const float* cscales  = (const float*)d_in[11];
    float* out            = (float*)d_out;

    cudaFuncSetAttribute(k_gemm_qkv_mma, cudaFuncAttributeMaxDynamicSharedMemorySize,
                         GEMM_SMEM);
    cudaFuncSetAttribute(k_gemm_out_mma, cudaFuncAttributeMaxDynamicSharedMemorySize,
                         GEMM_SMEM);
    cudaFuncSetAttribute(k_attn_mma, cudaFuncAttributeMaxDynamicSharedMemorySize,
                         ATTN_SMEM2);

    // QKV projection (mma.sync split-bf16; also emits pre-split K/V planes)
    {
        dim3 grid(QKVD / 128, (B_ * N_) / 128);
        k_gemm_qkv_mma<<<grid, 256, GEMM_SMEM>>>(x, qkv_w);
    }
    // pairwise bias MLP (tensorized; bias pre-scaled by alpha*log2e)
    {
        dim3 grid(N_ / 128, N_ / 8, B_);
        k_bias_mma<<<grid, 256>>>(coords, cscales, w1, b1, w2, b2, alpha);
    }
    // tensor-core flash attention (2 CTAs/SM, pre-split K/V, bias prefetch)
    {
        dim3 grid(N_ / 128, H_, B_);
        k_attn_mma<<<grid, 256, ATTN_SMEM2>>>(mask);
    }
    // output projection
    {
        dim3 grid(DM / 128, (B_ * N_) / 128);
        k_gemm_out_mma<<<grid, 256, GEMM_SMEM>>>(out_w, out_b, out);
    }
}

// round 13
// speedup vs baseline: 1.5425x; 1.5425x over previous
#include <cuda_runtime.h>
#include <cuda_bf16.h>
#include <cstdint>
#include <math.h>

#define B_   8
#define N_   1024
#define DM   512
#define H_   8
#define DH   64
#define QKVD 1536
#define NS_  1
#define L2E_ 1.4426950408889634f
#define SCALE_L2E (0.125f * L2E_)   // attn scale folded with log2(e)

// ---------------- scratch (device globals; no allocations) ----------------
__device__ float g_qkv[(size_t)B_ * N_ * QKVD];        //  50.3 MB  [b][n][3D]
__device__ float g_bias[(size_t)B_ * H_ * N_ * N_];    // 268.4 MB  pre-scaled by alpha*log2e
__device__ float g_att[(size_t)B_ * N_ * DM];          //  16.8 MB  [b][n][h*64+d]
// pre-split bf16 hi/lo K and V (written by the standalone convert kernel)
__device__ __nv_bfloat16 g_kh[(size_t)B_ * N_ * DM];
__device__ __nv_bfloat16 g_kl[(size_t)B_ * N_ * DM];
__device__ __nv_bfloat16 g_vh[(size_t)B_ * N_ * DM];
__device__ __nv_bfloat16 g_vl[(size_t)B_ * N_ * DM];

// =====================================================================
// common helpers
// =====================================================================
#define MMA16816(d, a, b) \
  asm volatile("mma.sync.aligned.m16n8k16.row.col.f32.bf16.bf16.f32 " \
    "{%0,%1,%2,%3}, {%4,%5,%6,%7}, {%8,%9}, {%0,%1,%2,%3};" \
    : "+f"((d)[0]), "+f"((d)[1]), "+f"((d)[2]), "+f"((d)[3]) \
    : "r"((a)[0]), "r"((a)[1]), "r"((a)[2]), "r"((a)[3]), \
      "r"((b)[0]), "r"((b)[1]))

#define LDMX2T(r0, r1, addr) \
  asm volatile("ldmatrix.sync.aligned.m8n8.x2.trans.shared.b16 {%0,%1}, [%2];" \
    : "=r"(r0), "=r"(r1) : "r"(addr))

__device__ __forceinline__ void split2(float a, float b, uint32_t& hi, uint32_t& lo)
{
    __nv_bfloat16 ha = __float2bfloat16(a), hb = __float2bfloat16(b);
    __nv_bfloat16 la = __float2bfloat16(a - __bfloat162float(ha));
    __nv_bfloat16 lb = __float2bfloat16(b - __bfloat162float(hb));
    __nv_bfloat162 h{ha, hb}, l{la, lb};
    hi = *(uint32_t*)&h; lo = *(uint32_t*)&l;
}

__device__ __forceinline__ void split_store(__nv_bfloat16* hp, __nv_bfloat16* lp,
                                            float4 v)
{
    uint32_t h0, l0, h1, l1;
    split2(v.x, v.y, h0, l0);
    split2(v.z, v.w, h1, l1);
    *(uint2*)hp = make_uint2(h0, h1);
    *(uint2*)lp = make_uint2(l0, l1);
}

// single-MUFU exp2 (softmax runs in base-2 domain)
__device__ __forceinline__ float ex2f(float x)
{
    float r;
    asm("ex2.approx.f32 %0, %1;" : "=f"(r) : "f"(x));
    return r;
}

// tanh-form GELU, single MUFU (tanh.approx): 4 FMA-class + 1 MUFU.
__device__ __forceinline__ float gelu_tanh(float t)
{
    float t2 = t * t;
    float u  = fmaf(0.0356774081f, t2, 0.7978845608f);
    float z  = t * u;
    float th;
    asm("tanh.approx.f32 %0, %1;" : "=f"(th) : "f"(z));
    float ht = 0.5f * t;
    return fmaf(ht, th, ht);
}

// =====================================================================
// mma.sync bf16 GEMM body — EXACT R11 version (no K/V epilogue split)
// =====================================================================
#define KC    16
#define LDSB  24
#define PLANE (128 * LDSB)
#define STAGE (4 * PLANE)
#define GEMM_SMEM (2 * STAGE * 2)

__device__ __forceinline__ void gemm_mma_body(
    const float* __restrict__ A, const float* __restrict__ W,
    const float* __restrict__ bias, float* __restrict__ C,
    int Nc, int K, int m0, int n0)
{
    extern __shared__ __nv_bfloat16 smb[];
    const int tid  = threadIdx.x;
    const int wid  = tid >> 5, lane = tid & 31;
    const int g    = lane >> 2, tg = lane & 3;
    const int wm   = (wid >> 2) * 64,  wn = (wid & 3) * 32;

    float acc[4][4][4];
    #pragma unroll
    for (int mt = 0; mt < 4; mt++)
        #pragma unroll
        for (int nt = 0; nt < 4; nt++)
            #pragma unroll
            for (int r = 0; r < 4; r++) acc[mt][nt][r] = 0.f;

    const int NCH = K / KC;
    const int prow0 = tid >> 2;
    const int pk4   = (tid & 3) << 2;
    float4 ra[2], rw[2];

    {
        #pragma unroll
        for (int t = 0; t < 2; t++) {
            int row = prow0 + t * 64;
            ra[t] = *(const float4*)&A[(size_t)(m0 + row) * K + pk4];
            rw[t] = *(const float4*)&W[(size_t)(n0 + row) * K + pk4];
        }
        __nv_bfloat16* s = smb;
        #pragma unroll
        for (int t = 0; t < 2; t++) {
            int row = prow0 + t * 64;
            int off = row * LDSB + pk4;
            split_store(s + off,             s + PLANE + off,     ra[t]);
            split_store(s + 2 * PLANE + off, s + 3 * PLANE + off, rw[t]);
        }
    }

    for (int c = 0; c < NCH; c++) {
        __syncthreads();

        if (c + 1 < NCH) {
            const int k0 = (c + 1) * KC;
            #pragma unroll
            for (int t = 0; t < 2; t++) {
                int row = prow0 + t * 64;
                ra[t] = *(const float4*)&A[(size_t)(m0 + row) * K + k0 + pk4];
                rw[t] = *(const float4*)&W[(size_t)(n0 + row) * K + k0 + pk4];
            }
        }

        {
            const __nv_bfloat16* Ah = smb + (c & 1) * STAGE;
            const __nv_bfloat16* Al = Ah + PLANE;
            const __nv_bfloat16* Bh = Ah + 2 * PLANE;
            const __nv_bfloat16* Bl = Ah + 3 * PLANE;

            uint32_t ah[4][4], al[4][4], bh[4][2], bl[4][2];
            #pragma unroll
            for (int mt = 0; mt < 4; mt++) {
                int base = (wm + mt * 16 + g) * LDSB + tg * 2;
                ah[mt][0] = *(const uint32_t*)(Ah + base);
                ah[mt][1] = *(const uint32_t*)(Ah + base + 8 * LDSB);
                ah[mt][2] = *(const uint32_t*)(Ah + base + 8);
                ah[mt][3] = *(const uint32_t*)(Ah + base + 8 * LDSB + 8);
                al[mt][0] = *(const uint32_t*)(Al + base);
                al[mt][1] = *(const uint32_t*)(Al + base + 8 * LDSB);
                al[mt][2] = *(const uint32_t*)(Al + base + 8);
                al[mt][3] = *(const uint32_t*)(Al + base + 8 * LDSB + 8);
            }
            #pragma unroll
            for (int nt = 0; nt < 4; nt++) {
                int base = (wn + nt * 8 + g) * LDSB + tg * 2;
                bh[nt][0] = *(const uint32_t*)(Bh + base);
                bh[nt][1] = *(const uint32_t*)(Bh + base + 8);
                bl[nt][0] = *(const uint32_t*)(Bl + base);
                bl[nt][1] = *(const uint32_t*)(Bl + base + 8);
            }
            #pragma unroll
            for (int mt = 0; mt < 4; mt++)
                #pragma unroll
                for (int nt = 0; nt < 4; nt++)
                    MMA16816(acc[mt][nt], ah[mt], bh[nt]);
            #pragma unroll
            for (int mt = 0; mt < 4; mt++)
                #pragma unroll
                for (int nt = 0; nt < 4; nt++)
                    MMA16816(acc[mt][nt], al[mt], bh[nt]);
            #pragma unroll
            for (int mt = 0; mt < 4; mt++)
                #pragma unroll
                for (int nt = 0; nt < 4; nt++)
                    MMA16816(acc[mt][nt], ah[mt], bl[nt]);
        }

        if (c + 1 < NCH) {
            __nv_bfloat16* s = smb + ((c + 1) & 1) * STAGE;
            #pragma unroll
            for (int t = 0; t < 2; t++) {
                int row = prow0 + t * 64;
                int off = row * LDSB + pk4;
                split_store(s + off,             s + PLANE + off,     ra[t]);
                split_store(s + 2 * PLANE + off, s + 3 * PLANE + off, rw[t]);
            }
        }
    }

    #pragma unroll
    for (int mt = 0; mt < 4; mt++) {
        #pragma unroll
        for (int nt = 0; nt < 4; nt++) {
            int row = m0 + wm + mt * 16 + g;
            int col = n0 + wn + nt * 8 + tg * 2;
            float bx = 0.f, by = 0.f;
            if (bias) { bx = bias[col]; by = bias[col + 1]; }
            *(float2*)&C[(size_t)row * Nc + col] =
                make_float2(acc[mt][nt][0] + bx, acc[mt][nt][1] + by);
            *(float2*)&C[(size_t)(row + 8) * Nc + col] =
                make_float2(acc[mt][nt][2] + bx, acc[mt][nt][3] + by);
        }
    }
}

__global__ void __launch_bounds__(256, 2)
k_gemm_qkv_mma(const float* __restrict__ x, const float* __restrict__ qkv_w)
{
    gemm_mma_body(x, qkv_w, nullptr, g_qkv, QKVD, DM,
                  blockIdx.y * 128, blockIdx.x * 128);
}

__global__ void __launch_bounds__(256, 2)
k_gemm_out_mma(const float* __restrict__ out_w, const float* __restrict__ out_b,
               float* __restrict__ out)
{
    gemm_mma_body(g_att, out_w, out_b, out, DM, DM,
                  blockIdx.y * 128, blockIdx.x * 128);
}

// =====================================================================
// Standalone K/V hi/lo split (memory-bound, ~12 µs): one thread per
// float4 of K (and the matching float4 of V).
// =====================================================================
__global__ void __launch_bounds__(256)
k_split_kv()
{
    size_t fi = (size_t)blockIdx.x * 256 + threadIdx.x;  // 0 .. B*N*128-1
    size_t row = fi >> 7;
    int c4 = (int)(fi & 127) << 2;
    size_t src = row * QKVD + DM + c4;
    size_t d = row * DM + c4;
    float4 kv = *(const float4*)&g_qkv[src];
    split_store(&g_kh[d], &g_kl[d], kv);
    float4 vv = *(const float4*)&g_qkv[src + DM];
    split_store(&g_vh[d], &g_vl[d], vv);
}

// =====================================================================
// Pairwise bias MLP — tensorized (R8-proven). Bias stored pre-scaled
// by alpha*log2(e) for the base-2 softmax.
// =====================================================================
__global__ void __launch_bounds__(256)
k_bias_mma(const float* __restrict__ coords, const float* __restrict__ cs,
           const float* __restrict__ w1, const float* __restrict__ b1,
           const float* __restrict__ w2, const float* __restrict__ b2,
           const float* __restrict__ alpha_p)
{
    __shared__ float sj[128 * 3];
    __shared__ float sci[8 * 3];
    __shared__ float sw1[128];
    __shared__ float sb1[32];
    __shared__ float sw2[256];
    __shared__ float sb2[8];
    __shared__ float sinv[3];
    __shared__ float salpha;

    const int tid = threadIdx.x;
    const int w = tid >> 5, lane = tid & 31;
    const int g = lane >> 2, tg = lane & 3;
    const int b = blockIdx.z;
    const int j0 = blockIdx.x * 128;
    const int i0 = blockIdx.y * 8;

    if (tid < 3) sinv[tid] = 1.0f / cs[tid];
    if (tid < 128) sw1[tid] = w1[tid];
    if (tid >= 128 && tid < 160) sb1[tid - 128] = b1[tid - 128];
    if (tid >= 160 && tid < 168) sb2[tid - 160] = b2[tid - 160];
    if (tid == 168) salpha = alpha_p[0] * L2E_;
    __syncthreads();
    for (int idx = tid; idx < 384; idx += 256) {
        int r = idx / 3, c = idx - r * 3;
        sj[idx] = coords[((size_t)(b * N_ + j0 + r)) * 3 + c] * sinv[c];
    }
    if (tid < 24) {
        int r = tid / 3, c = tid - r * 3;
        sci[tid] = coords[((size_t)(b * N_ + i0 + r)) * 3 + c] * sinv[c];
    }
    if (tid < 256) sw2[tid] = w2[tid];
    __syncthreads();

    uint32_t bw1h[4][2], bw1l[4][2];
    #pragma unroll
    for (int nt = 0; nt < 4; nt++) {
        float x0 = 0.f, x1 = 0.f;
        if (tg < 2) {
            x0 = sw1[(nt * 8 + g) * 4 + 2 * tg];
            x1 = sw1[(nt * 8 + g) * 4 + 2 * tg + 1];
        }
        split2(x0, x1, bw1h[nt][0], bw1l[nt][0]);
        bw1h[nt][1] = 0u; bw1l[nt][1] = 0u;
    }
    uint32_t bw2h[2][2], bw2l[2][2];
    #pragma unroll
    for (int kc = 0; kc < 2; kc++) {
        split2(sw2[g * 32 + 16 * kc + 2 * tg],
               sw2[g * 32 + 16 * kc + 2 * tg + 1], bw2h[kc][0], bw2l[kc][0]);
        split2(sw2[g * 32 + 16 * kc + 2 * tg + 8],
               sw2[g * 32 + 16 * kc + 2 * tg + 9], bw2h[kc][1], bw2l[kc][1]);
    }

    const int jlA = w * 16 + g;
    const int jlB = jlA + 8;
    const float cjAx = sj[jlA * 3], cjAy = sj[jlA * 3 + 1], cjAz = sj[jlA * 3 + 2];
    const float cjBx = sj[jlB * 3], cjBy = sj[jlB * 3 + 1], cjBz = sj[jlB * 3 + 2];
    const int jA = j0 + jlA, jB = j0 + jlB;
    const int h0 = 2 * tg, h1 = h0 + 1;
    const float bh0 = sb2[h0], bh1 = sb2[h1];

    #pragma unroll
    for (int ii = 0; ii < 8; ii++) {
        const int i = i0 + ii;
        const float cix = sci[ii * 3], ciy = sci[ii * 3 + 1], ciz = sci[ii * 3 + 2];

        float dxA = cix - cjAx, dyA = ciy - cjAy, dzA = ciz - cjAz;
        float dsA = sqrtf(fmaf(dxA, dxA, fmaf(dyA, dyA, dzA * dzA)));
        float dxB = cix - cjBx, dyB = ciy - cjBy, dzB = ciz - cjBz;
        float dsB = sqrtf(fmaf(dxB, dxB, fmaf(dyB, dyB, dzB * dzB)));

        float vA0 = tg == 0 ? dxA : (tg == 1 ? dzA : 0.f);
        float vA1 = tg == 0 ? dyA : (tg == 1 ? dsA : 0.f);
        float vB0 = tg == 0 ? dxB : (tg == 1 ? dzB : 0.f);
        float vB1 = tg == 0 ? dyB : (tg == 1 ? dsB : 0.f);
        uint32_t afh[4], afl[4];
        split2(vA0, vA1, afh[0], afl[0]);
        split2(vB0, vB1, afh[1], afl[1]);
        afh[2] = afh[3] = afl[2] = afl[3] = 0u;

        float d1[4][4];
        #pragma unroll
        for (int nt = 0; nt < 4; nt++) {
            d1[nt][0] = d1[nt][1] = d1[nt][2] = d1[nt][3] = 0.f;
            MMA16816(d1[nt], afh, bw1h[nt]);
            MMA16816(d1[nt], afl, bw1h[nt]);
            MMA16816(d1[nt], afh, bw1l[nt]);
        }

        float gv[4][4];
        #pragma unroll
        for (int nt = 0; nt < 4; nt++) {
            float ba = sb1[8 * nt + 2 * tg], bb = sb1[8 * nt + 2 * tg + 1];
            gv[nt][0] = gelu_tanh(d1[nt][0] + ba);
            gv[nt][1] = gelu_tanh(d1[nt][1] + bb);
            gv[nt][2] = gelu_tanh(d1[nt][2] + ba);
            gv[nt][3] = gelu_tanh(d1[nt][3] + bb);
        }

        float d2[4] = {0.f, 0.f, 0.f, 0.f};
        #pragma unroll
        for (int kc = 0; kc < 2; kc++) {
            uint32_t a2h[4], a2l[4];
            split2(gv[2 * kc][0],     gv[2 * kc][1],     a2h[0], a2l[0]);
            split2(gv[2 * kc][2],     gv[2 * kc][3],     a2h[1], a2l[1]);
            split2(gv[2 * kc + 1][0], gv[2 * kc + 1][1], a2h[2], a2l[2]);
            split2(gv[2 * kc + 1][2], gv[2 * kc + 1][3], a2h[3], a2l[3]);
            MMA16816(d2, a2h, bw2h[kc]);
            MMA16816(d2, a2l, bw2h[kc]);
            MMA16816(d2, a2h, bw2l[kc]);
        }

        float si = (i >= NS_) ? salpha : 0.f;
        float sA = (jA >= NS_) ? si : 0.f;
        float sB = si;
        size_t r0 = ((size_t)(b * H_ + h0) * N_ + i) * N_;
        size_t r1 = ((size_t)(b * H_ + h1) * N_ + i) * N_;
        g_bias[r0 + jA] = sA * (d2[0] + bh0);
        g_bias[r1 + jA] = sA * (d2[1] + bh1);
        g_bias[r0 + jB] = sB * (d2[2] + bh0);
        g_bias[r1 + jB] = sB * (d2[3] + bh1);
    }
}

// =====================================================================
// Tensor-core flash attention — base-2 softmax, 2 CTAs/SM, bias
// prefetch; K/V loaded PRE-SPLIT (bf16 hi/lo) from the convert kernel.
// =====================================================================
#define LQ 72
#define ATTN_SMEM2 (36864 * 2 + 64 * 4)

__global__ void __launch_bounds__(256, 2)
k_attn_mma(const unsigned char* __restrict__ mask)
{
    extern __shared__ __nv_bfloat16 sma[];
    __nv_bfloat16* Qh = sma;
    __nv_bfloat16* Ql = sma + 9216;
    __nv_bfloat16* Kh = sma + 18432;
    __nv_bfloat16* Kl = sma + 23040;
    __nv_bfloat16* Vh = sma + 27648;
    __nv_bfloat16* Vl = sma + 32256;
    float* madd = (float*)(sma + 36864);

    const int b = blockIdx.z, h = blockIdx.y;
    const int i0 = blockIdx.x * 128;
    const int tid = threadIdx.x;
    const int w = tid >> 5, lane = tid & 31;
    const int g = lane >> 2, tg = lane & 3;

    const uint32_t vh_u32 = (uint32_t)__cvta_generic_to_shared(Vh);
    const uint32_t vl_u32 = (uint32_t)__cvta_generic_to_shared(Vl);

    #pragma unroll
    for (int t = 0; t < 8; t++) {
        int f = tid + t * 256;
        int row = f >> 4;
        int c4 = (f & 15) << 2;
        float4 v = *(const float4*)&g_qkv[((size_t)(b * N_ + i0 + row)) * QKVD + h * DH + c4];
        split_store(Qh + row * LQ + c4, Ql + row * LQ + c4, v);
    }

    float oacc[8][4];
    #pragma unroll
    for (int nt = 0; nt < 8; nt++)
        #pragma unroll
        for (int r = 0; r < 4; r++) oacc[nt][r] = 0.f;
    float m0r = -INFINITY, m1r = -INFINITY, l0r = 0.f, l1r = 0.f;

    const size_t bias_row0 = ((size_t)(b * H_ + h) * N_ + (i0 + w * 16 + g)) * N_;
    const int qrow = (w * 16 + g) * LQ + tg * 2;

    for (int j0 = 0; j0 < N_; j0 += 64) {
        __syncthreads();

        // K/V fill: straight bf16 hi/lo copies (pre-split)
        #pragma unroll
        for (int t = 0; t < 4; t++) {
            int f = tid + t * 256;
            int row = f >> 4;
            int c4 = (f & 15) << 2;
            size_t idx = ((size_t)(b * N_ + j0 + row)) * DM + h * DH + c4;
            int off = row * LQ + c4;
            *(uint2*)(Kh + off) = *(const uint2*)&g_kh[idx];
            *(uint2*)(Kl + off) = *(const uint2*)&g_kl[idx];
            *(uint2*)(Vh + off) = *(const uint2*)&g_vh[idx];
            *(uint2*)(Vl + off) = *(const uint2*)&g_vl[idx];
        }
        if (tid < 64)
            madd[tid] = mask[(size_t)b * N_ + j0 + tid] ? -1e30f : 0.0f;
        __syncthreads();

        // prefetch bias tile into registers (overlaps the S-MMA block)
        const float* bp0 = &g_bias[bias_row0 + j0];
        const float* bp1 = bp0 + 8 * N_;
        float2 bz0r[8], bz1r[8];
        #pragma unroll
        for (int nt = 0; nt < 8; nt++) {
            int col = 8 * nt + tg * 2;
            bz0r[nt] = *(const float2*)&bp0[col];
            bz1r[nt] = *(const float2*)&bp1[col];
        }

        float sacc[8][4];
        #pragma unroll
        for (int nt = 0; nt < 8; nt++)
            #pragma unroll
            for (int r = 0; r < 4; r++) sacc[nt][r] = 0.f;

        #pragma unroll
        for (int kc = 0; kc < 4; kc++) {
            int qb = qrow + kc * 16;
            uint32_t qh[4], ql[4];
            qh[0] = *(const uint32_t*)(Qh + qb);
            qh[1] = *(const uint32_t*)(Qh + qb + 8 * LQ);
            qh[2] = *(const uint32_t*)(Qh + qb + 8);
            qh[3] = *(const uint32_t*)(Qh + qb + 8 * LQ + 8);
            ql[0] = *(const uint32_t*)(Ql + qb);
            ql[1] = *(const uint32_t*)(Ql + qb + 8 * LQ);
            ql[2] = *(const uint32_t*)(Ql + qb + 8);
            ql[3] = *(const uint32_t*)(Ql + qb + 8 * LQ + 8);
            #pragma unroll
            for (int nt = 0; nt < 8; nt++) {
                int kb = (8 * nt + g) * LQ + kc * 16 + tg * 2;
                uint32_t bh[2], bl[2];
                bh[0] = *(const uint32_t*)(Kh + kb);
                bh[1] = *(const uint32_t*)(Kh + kb + 8);
                bl[0] = *(const uint32_t*)(Kl + kb);
                bl[1] = *(const uint32_t*)(Kl + kb + 8);
                MMA16816(sacc[nt], qh, bh);
                MMA16816(sacc[nt], ql, bh);
                MMA16816(sacc[nt], qh, bl);
            }
        }

        // logits (base-2): S*(scale*log2e) + prefetched bias + mask
        #pragma unroll
        for (int nt = 0; nt < 8; nt++) {
            int col = 8 * nt + tg * 2;
            float2 mz = *(float2*)&madd[col];
            sacc[nt][0] = fmaf(sacc[nt][0], SCALE_L2E, bz0r[nt].x) + mz.x;
            sacc[nt][1] = fmaf(sacc[nt][1], SCALE_L2E, bz0r[nt].y) + mz.y;
            sacc[nt][2] = fmaf(sacc[nt][2], SCALE_L2E, bz1r[nt].x) + mz.x;
            sacc[nt][3] = fmaf(sacc[nt][3], SCALE_L2E, bz1r[nt].y) + mz.y;
        }

        float mx0 = -INFINITY, mx1 = -INFINITY;
        #pragma unroll
        for (int nt = 0; nt < 8; nt++) {
            mx0 = fmaxf(mx0, fmaxf(sacc[nt][0], sacc[nt][1]));
            mx1 = fmaxf(mx1, fmaxf(sacc[nt][2], sacc[nt][3]));
        }
        mx0 = fmaxf(mx0, __shfl_xor_sync(0xffffffffu, mx0, 1));
        mx0 = fmaxf(mx0, __shfl_xor_sync(0xffffffffu, mx0, 2));
        mx1 = fmaxf(mx1, __shfl_xor_sync(0xffffffffu, mx1, 1));
        mx1 = fmaxf(mx1, __shfl_xor_sync(0xffffffffu, mx1, 2));

        float mn0 = fmaxf(m0r, mx0), mn1 = fmaxf(m1r, mx1);
        float a0 = ex2f(m0r - mn0), a1 = ex2f(m1r - mn1);
        m0r = mn0; m1r = mn1;

        float rs0 = 0.f, rs1 = 0.f;
        #pragma unroll
        for (int nt = 0; nt < 8; nt++) {
            float p0 = ex2f(sacc[nt][0] - mn0);
            float p1 = ex2f(sacc[nt][1] - mn0);
            float p2 = ex2f(sacc[nt][2] - mn1);
            float p3 = ex2f(sacc[nt][3] - mn1);
            sacc[nt][0] = p0; sacc[nt][1] = p1;
            sacc[nt][2] = p2; sacc[nt][3] = p3;
            rs0 += p0 + p1; rs1 += p2 + p3;
        }
        rs0 += __shfl_xor_sync(0xffffffffu, rs0, 1);
        rs0 += __shfl_xor_sync(0xffffffffu, rs0, 2);
        rs1 += __shfl_xor_sync(0xffffffffu, rs1, 1);
        rs1 += __shfl_xor_sync(0xffffffffu, rs1, 2);
        l0r = l0r * a0 + rs0;
        l1r = l1r * a1 + rs1;
        #pragma unroll
        for (int nt = 0; nt < 8; nt++) {
            oacc[nt][0] *= a0; oacc[nt][1] *= a0;
            oacc[nt][2] *= a1; oacc[nt][3] *= a1;
        }

        #pragma unroll
        for (int kc = 0; kc < 4; kc++) {
            uint32_t ph[4], pl[4];
            split2(sacc[2 * kc][0],     sacc[2 * kc][1],     ph[0], pl[0]);
            split2(sacc[2 * kc][2],     sacc[2 * kc][3],     ph[1], pl[1]);
            split2(sacc[2 * kc + 1][0], sacc[2 * kc + 1][1], ph[2], pl[2]);
            split2(sacc[2 * kc + 1][2], sacc[2 * kc + 1][3], ph[3], pl[3]);

            uint32_t rowoff = (uint32_t)((16 * kc + (lane & 15)) * LQ) * 2;
            #pragma unroll
            for (int ntd = 0; ntd < 8; ntd++) {
                uint32_t bh[2], bl[2];
                LDMX2T(bh[0], bh[1], vh_u32 + rowoff + ntd * 16);
                LDMX2T(bl[0], bl[1], vl_u32 + rowoff + ntd * 16);
                MMA16816(oacc[ntd], ph, bh);
                MMA16816(oacc[ntd], pl, bh);
                MMA16816(oacc[ntd], ph, bl);
            }
        }
    }

    float inv0 = 1.0f / l0r, inv1 = 1.0f / l1r;
    const size_t orow0 = ((size_t)(b * N_ + i0 + w * 16 + g)) * DM + h * DH;
    const size_t orow1 = orow0 + (size_t)8 * DM;
    #pragma unroll
    for (int nt = 0; nt < 8; nt++) {
        int col = 8 * nt + tg * 2;
        *(float2*)&g_att[orow0 + col] =
            make_float2(oacc[nt][0] * inv0, oacc[nt][1] * inv0);
        *(float2*)&g_att[orow1 + col] =
            make_float2(oacc[nt][2] * inv1, oacc[nt][3] * inv1);
    }
}

// =====================================================================
extern "C" void kernel_launch(void* const* d_in, const int* in_sizes, int n_in,
                              void* d_out, int out_size)
{
    const float* x        = (const float*)d_in[0];
    const float* coords   = (const float*)d_in[1];
    const unsigned char* mask = (const unsigned char*)d_in[2];
    const float* qkv_w    = (const float*)d_in[3];
    const float* out_w    = (const float*)d_in[4];
    const float* out_b    = (const float*)d_in[5];
    const float* alpha    = (const float*)d_in[6];
    const float* w1       = (const float*)d_in[7];
    const float* b1       = (const float*)d_in[8];
    const float* w2       = (const float*)d_in[9];
    const float* b2       = (const float*)d_in[10];
    const float* cscales  = (const float*)d_in[11];
    float* out            = (float*)d_out;

    cudaFuncSetAttribute(k_gemm_qkv_mma, cudaFuncAttributeMaxDynamicSharedMemorySize,
                         GEMM_SMEM);
    cudaFuncSetAttribute(k_gemm_out_mma, cudaFuncAttributeMaxDynamicSharedMemorySize,
                         GEMM_SMEM);
    cudaFuncSetAttribute(k_attn_mma, cudaFuncAttributeMaxDynamicSharedMemorySize,
                         ATTN_SMEM2);

    // QKV projection (mma.sync split-bf16, R11-exact)
    {
        dim3 grid(QKVD / 128, (B_ * N_) / 128);
        k_gemm_qkv_mma<<<grid, 256, GEMM_SMEM>>>(x, qkv_w);
    }
    // standalone K/V hi/lo split (memory-bound, ~12 us)
    {
        k_split_kv<<<(B_ * N_ * (DM / 4)) / 256, 256>>>();
    }
    // pairwise bias MLP (tensorized; bias pre-scaled by alpha*log2e)
    {
        dim3 grid(N_ / 128, N_ / 8, B_);
        k_bias_mma<<<grid, 256>>>(coords, cscales, w1, b1, w2, b2, alpha);
    }
    // tensor-core flash attention (2 CTAs/SM, pre-split K/V, bias prefetch)
    {
        dim3 grid(N_ / 128, H_, B_);
        k_attn_mma<<<grid, 256, ATTN_SMEM2>>>(mask);
    }
    // output projection
    {
        dim3 grid(DM / 128, (B_ * N_) / 128);
        k_gemm_out_mma<<<grid, 256, GEMM_SMEM>>>(out_w, out_b, out);
    }
}

// round 16
// speedup vs baseline: 1.6534x; 1.0719x over previous
#include <cuda_runtime.h>
#include <cuda_bf16.h>
#include <cuda_fp16.h>
#include <cstdint>
#include <math.h>

#define B_   8
#define N_   1024
#define DM   512
#define H_   8
#define DH   64
#define QKVD 1536
#define NS_  1
#define L2E_ 1.4426950408889634f
#define SCALE_L2E (0.125f * L2E_)   // attn scale folded with log2(e)

// ---------------- scratch (device globals; no allocations) ----------------
__device__ float g_qkv[(size_t)B_ * N_ * QKVD];        //  50.3 MB  [b][n][3D]
__device__ float g_bias[(size_t)B_ * H_ * N_ * N_];    // 268.4 MB  pre-scaled by alpha*log2e
__device__ float g_att[(size_t)B_ * N_ * DM];          //  16.8 MB  [b][n][h*64+d]

// =====================================================================
// common helpers
// =====================================================================
#define MMA16816(d, a, b) \
  asm volatile("mma.sync.aligned.m16n8k16.row.col.f32.bf16.bf16.f32 " \
    "{%0,%1,%2,%3}, {%4,%5,%6,%7}, {%8,%9}, {%0,%1,%2,%3};" \
    : "+f"((d)[0]), "+f"((d)[1]), "+f"((d)[2]), "+f"((d)[3]) \
    : "r"((a)[0]), "r"((a)[1]), "r"((a)[2]), "r"((a)[3]), \
      "r"((b)[0]), "r"((b)[1]))

// fp16 variant (same shape/throughput; used for PV where fp16's 11-bit
// mantissa gives 4x finer V representation than bf16)
#define MMA16816H(d, a, b) \
  asm volatile("mma.sync.aligned.m16n8k16.row.col.f32.f16.f16.f32 " \
    "{%0,%1,%2,%3}, {%4,%5,%6,%7}, {%8,%9}, {%0,%1,%2,%3};" \
    : "+f"((d)[0]), "+f"((d)[1]), "+f"((d)[2]), "+f"((d)[3]) \
    : "r"((a)[0]), "r"((a)[1]), "r"((a)[2]), "r"((a)[3]), \
      "r"((b)[0]), "r"((b)[1]))

#define LDMX2T(r0, r1, addr) \
  asm volatile("ldmatrix.sync.aligned.m8n8.x2.trans.shared.b16 {%0,%1}, [%2];" \
    : "=r"(r0), "=r"(r1) : "r"(addr))

__device__ __forceinline__ void split2(float a, float b, uint32_t& hi, uint32_t& lo)
{
    __nv_bfloat16 ha = __float2bfloat16(a), hb = __float2bfloat16(b);
    __nv_bfloat16 la = __float2bfloat16(a - __bfloat162float(ha));
    __nv_bfloat16 lb = __float2bfloat16(b - __bfloat162float(hb));
    __nv_bfloat162 h{ha, hb}, l{la, lb};
    hi = *(uint32_t*)&h; lo = *(uint32_t*)&l;
}

// fp16 hi/lo split (for P in the PV product)
__device__ __forceinline__ void split2h(float a, float b, uint32_t& hi, uint32_t& lo)
{
    __half ha = __float2half_rn(a), hb = __float2half_rn(b);
    __half la = __float2half_rn(a - __half2float(ha));
    __half lb = __float2half_rn(b - __half2float(hb));
    __half2 h{ha, hb}, l{la, lb};
    hi = *(uint32_t*)&h; lo = *(uint32_t*)&l;
}

__device__ __forceinline__ void split_store(__nv_bfloat16* hp, __nv_bfloat16* lp,
                                            float4 v)
{
    uint32_t h0, l0, h1, l1;
    split2(v.x, v.y, h0, l0);
    split2(v.z, v.w, h1, l1);
    *(uint2*)hp = make_uint2(h0, h1);
    *(uint2*)lp = make_uint2(l0, l1);
}

// fp16 single conversion store (for V)
__device__ __forceinline__ void cvt_store_h16(__half* hp, float4 v)
{
    __half2 a{__float2half_rn(v.x), __float2half_rn(v.y)};
    __half2 b{__float2half_rn(v.z), __float2half_rn(v.w)};
    *(uint2*)hp = make_uint2(*(uint32_t*)&a, *(uint32_t*)&b);
}

// single-MUFU exp2 (softmax runs in base-2 domain)
__device__ __forceinline__ float ex2f(float x)
{
    float r;
    asm("ex2.approx.f32 %0, %1;" : "=f"(r) : "f"(x));
    return r;
}

// tanh-form GELU, single MUFU (tanh.approx): 4 FMA-class + 1 MUFU.
__device__ __forceinline__ float gelu_tanh(float t)
{
    float t2 = t * t;
    float u  = fmaf(0.0356774081f, t2, 0.7978845608f);
    float z  = t * u;
    float th;
    asm("tanh.approx.f32 %0, %1;" : "=f"(th) : "f"(z));
    float ht = 0.5f * t;
    return fmaf(ht, th, ht);
}

// =====================================================================
// mma.sync bf16 GEMM body (R5/R11-proven, unchanged)
// =====================================================================
#define KC    16
#define LDSB  24
#define PLANE (128 * LDSB)
#define STAGE (4 * PLANE)
#define GEMM_SMEM (2 * STAGE * 2)

__device__ __forceinline__ void gemm_mma_body(
    const float* __restrict__ A, const float* __restrict__ W,
    const float* __restrict__ bias, float* __restrict__ C,
    int Nc, int K, int m0, int n0)
{
    extern __shared__ __nv_bfloat16 smb[];
    const int tid  = threadIdx.x;
    const int wid  = tid >> 5, lane = tid & 31;
    const int g    = lane >> 2, tg = lane & 3;
    const int wm   = (wid >> 2) * 64,  wn = (wid & 3) * 32;

    float acc[4][4][4];
    #pragma unroll
    for (int mt = 0; mt < 4; mt++)
        #pragma unroll
        for (int nt = 0; nt < 4; nt++)
            #pragma unroll
            for (int r = 0; r < 4; r++) acc[mt][nt][r] = 0.f;

    const int NCH = K / KC;
    const int prow0 = tid >> 2;
    const int pk4   = (tid & 3) << 2;
    float4 ra[2], rw[2];

    {
        #pragma unroll
        for (int t = 0; t < 2; t++) {
            int row = prow0 + t * 64;
            ra[t] = *(const float4*)&A[(size_t)(m0 + row) * K + pk4];
            rw[t] = *(const float4*)&W[(size_t)(n0 + row) * K + pk4];
        }
        __nv_bfloat16* s = smb;
        #pragma unroll
        for (int t = 0; t < 2; t++) {
            int row = prow0 + t * 64;
            int off = row * LDSB + pk4;
            split_store(s + off,             s + PLANE + off,     ra[t]);
            split_store(s + 2 * PLANE + off, s + 3 * PLANE + off, rw[t]);
        }
    }

    for (int c = 0; c < NCH; c++) {
        __syncthreads();

        if (c + 1 < NCH) {
            const int k0 = (c + 1) * KC;
            #pragma unroll
            for (int t = 0; t < 2; t++) {
                int row = prow0 + t * 64;
                ra[t] = *(const float4*)&A[(size_t)(m0 + row) * K + k0 + pk4];
                rw[t] = *(const float4*)&W[(size_t)(n0 + row) * K + k0 + pk4];
            }
        }

        {
            const __nv_bfloat16* Ah = smb + (c & 1) * STAGE;
            const __nv_bfloat16* Al = Ah + PLANE;
            const __nv_bfloat16* Bh = Ah + 2 * PLANE;
            const __nv_bfloat16* Bl = Ah + 3 * PLANE;

            uint32_t ah[4][4], al[4][4], bh[4][2], bl[4][2];
            #pragma unroll
            for (int mt = 0; mt < 4; mt++) {
                int base = (wm + mt * 16 + g) * LDSB + tg * 2;
                ah[mt][0] = *(const uint32_t*)(Ah + base);
                ah[mt][1] = *(const uint32_t*)(Ah + base + 8 * LDSB);
                ah[mt][2] = *(const uint32_t*)(Ah + base + 8);
                ah[mt][3] = *(const uint32_t*)(Ah + base + 8 * LDSB + 8);
                al[mt][0] = *(const uint32_t*)(Al + base);
                al[mt][1] = *(const uint32_t*)(Al + base + 8 * LDSB);
                al[mt][2] = *(const uint32_t*)(Al + base + 8);
                al[mt][3] = *(const uint32_t*)(Al + base + 8 * LDSB + 8);
            }
            #pragma unroll
            for (int nt = 0; nt < 4; nt++) {
                int base = (wn + nt * 8 + g) * LDSB + tg * 2;
                bh[nt][0] = *(const uint32_t*)(Bh + base);
                bh[nt][1] = *(const uint32_t*)(Bh + base + 8);
                bl[nt][0] = *(const uint32_t*)(Bl + base);
                bl[nt][1] = *(const uint32_t*)(Bl + base + 8);
            }
            #pragma unroll
            for (int mt = 0; mt < 4; mt++)
                #pragma unroll
                for (int nt = 0; nt < 4; nt++)
                    MMA16816(acc[mt][nt], ah[mt], bh[nt]);
            #pragma unroll
            for (int mt = 0; mt < 4; mt++)
                #pragma unroll
                for (int nt = 0; nt < 4; nt++)
                    MMA16816(acc[mt][nt], al[mt], bh[nt]);
            #pragma unroll
            for (int mt = 0; mt < 4; mt++)
                #pragma unroll
                for (int nt = 0; nt < 4; nt++)
                    MMA16816(acc[mt][nt], ah[mt], bl[nt]);
        }

        if (c + 1 < NCH) {
            __nv_bfloat16* s = smb + ((c + 1) & 1) * STAGE;
            #pragma unroll
            for (int t = 0; t < 2; t++) {
                int row = prow0 + t * 64;
                int off = row * LDSB + pk4;
                split_store(s + off,             s + PLANE + off,     ra[t]);
                split_store(s + 2 * PLANE + off, s + 3 * PLANE + off, rw[t]);
            }
        }
    }

    #pragma unroll
    for (int mt = 0; mt < 4; mt++) {
        #pragma unroll
        for (int nt = 0; nt < 4; nt++) {
            int row = m0 + wm + mt * 16 + g;
            int col = n0 + wn + nt * 8 + tg * 2;
            float bx = 0.f, by = 0.f;
            if (bias) { bx = bias[col]; by = bias[col + 1]; }
            *(float2*)&C[(size_t)row * Nc + col] =
                make_float2(acc[mt][nt][0] + bx, acc[mt][nt][1] + by);
            *(float2*)&C[(size_t)(row + 8) * Nc + col] =
                make_float2(acc[mt][nt][2] + bx, acc[mt][nt][3] + by);
        }
    }
}

__global__ void __launch_bounds__(256, 2)
k_gemm_qkv_mma(const float* __restrict__ x, const float* __restrict__ qkv_w)
{
    gemm_mma_body(x, qkv_w, nullptr, g_qkv, QKVD, DM,
                  blockIdx.y * 128, blockIdx.x * 128);
}

__global__ void __launch_bounds__(256, 2)
k_gemm_out_mma(const float* __restrict__ out_w, const float* __restrict__ out_b,
               float* __restrict__ out)
{
    gemm_mma_body(g_att, out_w, out_b, out, DM, DM,
                  blockIdx.y * 128, blockIdx.x * 128);
}

// =====================================================================
// Pairwise bias MLP — tensorized (R8-proven). Bias stored pre-scaled
// by alpha*log2(e) for the base-2 softmax.
// =====================================================================
__global__ void __launch_bounds__(256)
k_bias_mma(const float* __restrict__ coords, const float* __restrict__ cs,
           const float* __restrict__ w1, const float* __restrict__ b1,
           const float* __restrict__ w2, const float* __restrict__ b2,
           const float* __restrict__ alpha_p)
{
    __shared__ float sj[128 * 3];
    __shared__ float sci[8 * 3];
    __shared__ float sw1[128];
    __shared__ float sb1[32];
    __shared__ float sw2[256];
    __shared__ float sb2[8];
    __shared__ float sinv[3];
    __shared__ float salpha;

    const int tid = threadIdx.x;
    const int w = tid >> 5, lane = tid & 31;
    const int g = lane >> 2, tg = lane & 3;
    const int b = blockIdx.z;
    const int j0 = blockIdx.x * 128;
    const int i0 = blockIdx.y * 8;

    if (tid < 3) sinv[tid] = 1.0f / cs[tid];
    if (tid < 128) sw1[tid] = w1[tid];
    if (tid >= 128 && tid < 160) sb1[tid - 128] = b1[tid - 128];
    if (tid >= 160 && tid < 168) sb2[tid - 160] = b2[tid - 160];
    if (tid == 168) salpha = alpha_p[0] * L2E_;
    __syncthreads();
    for (int idx = tid; idx < 384; idx += 256) {
        int r = idx / 3, c = idx - r * 3;
        sj[idx] = coords[((size_t)(b * N_ + j0 + r)) * 3 + c] * sinv[c];
    }
    if (tid < 24) {
        int r = tid / 3, c = tid - r * 3;
        sci[tid] = coords[((size_t)(b * N_ + i0 + r)) * 3 + c] * sinv[c];
    }
    if (tid < 256) sw2[tid] = w2[tid];
    __syncthreads();

    uint32_t bw1h[4][2], bw1l[4][2];
    #pragma unroll
    for (int nt = 0; nt < 4; nt++) {
        float x0 = 0.f, x1 = 0.f;
        if (tg < 2) {
            x0 = sw1[(nt * 8 + g) * 4 + 2 * tg];
            x1 = sw1[(nt * 8 + g) * 4 + 2 * tg + 1];
        }
        split2(x0, x1, bw1h[nt][0], bw1l[nt][0]);
        bw1h[nt][1] = 0u; bw1l[nt][1] = 0u;
    }
    uint32_t bw2h[2][2], bw2l[2][2];
    #pragma unroll
    for (int kc = 0; kc < 2; kc++) {
        split2(sw2[g * 32 + 16 * kc + 2 * tg],
               sw2[g * 32 + 16 * kc + 2 * tg + 1], bw2h[kc][0], bw2l[kc][0]);
        split2(sw2[g * 32 + 16 * kc + 2 * tg + 8],
               sw2[g * 32 + 16 * kc + 2 * tg + 9], bw2h[kc][1], bw2l[kc][1]);
    }

    const int jlA = w * 16 + g;
    const int jlB = jlA + 8;
    const float cjAx = sj[jlA * 3], cjAy = sj[jlA * 3 + 1], cjAz = sj[jlA * 3 + 2];
    const float cjBx = sj[jlB * 3], cjBy = sj[jlB * 3 + 1], cjBz = sj[jlB * 3 + 2];
    const int jA = j0 + jlA, jB = j0 + jlB;
    const int h0 = 2 * tg, h1 = h0 + 1;
    const float bh0 = sb2[h0], bh1 = sb2[h1];

    #pragma unroll
    for (int ii = 0; ii < 8; ii++) {
        const int i = i0 + ii;
        const float cix = sci[ii * 3], ciy = sci[ii * 3 + 1], ciz = sci[ii * 3 + 2];

        float dxA = cix - cjAx, dyA = ciy - cjAy, dzA = ciz - cjAz;
        float dsA = sqrtf(fmaf(dxA, dxA, fmaf(dyA, dyA, dzA * dzA)));
        float dxB = cix - cjBx, dyB = ciy - cjBy, dzB = ciz - cjBz;
        float dsB = sqrtf(fmaf(dxB, dxB, fmaf(dyB, dyB, dzB * dzB)));

        float vA0 = tg == 0 ? dxA : (tg == 1 ? dzA : 0.f);
        float vA1 = tg == 0 ? dyA : (tg == 1 ? dsA : 0.f);
        float vB0 = tg == 0 ? dxB : (tg == 1 ? dzB : 0.f);
        float vB1 = tg == 0 ? dyB : (tg == 1 ? dsB : 0.f);
        uint32_t afh[4], afl[4];
        split2(vA0, vA1, afh[0], afl[0]);
        split2(vB0, vB1, afh[1], afl[1]);
        afh[2] = afh[3] = afl[2] = afl[3] = 0u;

        float d1[4][4];
        #pragma unroll
        for (int nt = 0; nt < 4; nt++) {
            d1[nt][0] = d1[nt][1] = d1[nt][2] = d1[nt][3] = 0.f;
            MMA16816(d1[nt], afh, bw1h[nt]);
            MMA16816(d1[nt], afl, bw1h[nt]);
            MMA16816(d1[nt], afh, bw1l[nt]);
        }

        float gv[4][4];
        #pragma unroll
        for (int nt = 0; nt < 4; nt++) {
            float ba = sb1[8 * nt + 2 * tg], bb = sb1[8 * nt + 2 * tg + 1];
            gv[nt][0] = gelu_tanh(d1[nt][0] + ba);
            gv[nt][1] = gelu_tanh(d1[nt][1] + bb);
            gv[nt][2] = gelu_tanh(d1[nt][2] + ba);
            gv[nt][3] = gelu_tanh(d1[nt][3] + bb);
        }

        float d2[4] = {0.f, 0.f, 0.f, 0.f};
        #pragma unroll
        for (int kc = 0; kc < 2; kc++) {
            uint32_t a2h[4], a2l[4];
            split2(gv[2 * kc][0],     gv[2 * kc][1],     a2h[0], a2l[0]);
            split2(gv[2 * kc][2],     gv[2 * kc][3],     a2h[1], a2l[1]);
            split2(gv[2 * kc + 1][0], gv[2 * kc + 1][1], a2h[2], a2l[2]);
            split2(gv[2 * kc + 1][2], gv[2 * kc + 1][3], a2h[3], a2l[3]);
            MMA16816(d2, a2h, bw2h[kc]);
            MMA16816(d2, a2l, bw2h[kc]);
            MMA16816(d2, a2h, bw2l[kc]);
        }

        float si = (i >= NS_) ? salpha : 0.f;
        float sA = (jA >= NS_) ? si : 0.f;
        float sB = si;
        size_t r0 = ((size_t)(b * H_ + h0) * N_ + i) * N_;
        size_t r1 = ((size_t)(b * H_ + h1) * N_ + i) * N_;
        g_bias[r0 + jA] = sA * (d2[0] + bh0);
        g_bias[r1 + jA] = sA * (d2[1] + bh1);
        g_bias[r0 + jB] = sB * (d2[2] + bh0);
        g_bias[r1 + jB] = sB * (d2[3] + bh1);
    }
}

// =====================================================================
// Tensor-core flash attention — base-2 softmax, 2 CTAs/SM, bias
// prefetch. S = QK^T: bf16 3-pass (unchanged, feeds exponents).
// O = P V: fp16 2-pass — P split hi/lo in fp16 (error ~2^-22), V single
// fp16 (rel 2^-11, 4x finer than bf16; R15's bf16-V measured 1.29e-3,
// so fp16-V predicts ~3.2e-4).
// smem (bf16 units): Qh@0 Ql@9216 Kh@18432 Kl@23040 Vh(fp16)@27648 + madd
// =====================================================================
#define LQ 72
#define ATTN_SMEM2 (32256 * 2 + 64 * 4)

__global__ void __launch_bounds__(256, 2)
k_attn_mma(const unsigned char* __restrict__ mask)
{
    extern __shared__ __nv_bfloat16 sma[];
    __nv_bfloat16* Qh = sma;
    __nv_bfloat16* Ql = sma + 9216;
    __nv_bfloat16* Kh = sma + 18432;
    __nv_bfloat16* Kl = sma + 23040;
    __half*        Vh = (__half*)(sma + 27648);
    float* madd = (float*)(sma + 32256);

    const int b = blockIdx.z, h = blockIdx.y;
    const int i0 = blockIdx.x * 128;
    const int tid = threadIdx.x;
    const int w = tid >> 5, lane = tid & 31;
    const int g = lane >> 2, tg = lane & 3;

    const uint32_t vh_u32 = (uint32_t)__cvta_generic_to_shared(Vh);

    #pragma unroll
    for (int t = 0; t < 8; t++) {
        int f = tid + t * 256;
        int row = f >> 4;
        int c4 = (f & 15) << 2;
        float4 v = *(const float4*)&g_qkv[((size_t)(b * N_ + i0 + row)) * QKVD + h * DH + c4];
        split_store(Qh + row * LQ + c4, Ql + row * LQ + c4, v);
    }

    float oacc[8][4];
    #pragma unroll
    for (int nt = 0; nt < 8; nt++)
        #pragma unroll
        for (int r = 0; r < 4; r++) oacc[nt][r] = 0.f;
    float m0r = -INFINITY, m1r = -INFINITY, l0r = 0.f, l1r = 0.f;

    const size_t bias_row0 = ((size_t)(b * H_ + h) * N_ + (i0 + w * 16 + g)) * N_;
    const int qrow = (w * 16 + g) * LQ + tg * 2;

    for (int j0 = 0; j0 < N_; j0 += 64) {
        __syncthreads();

        // K/V fill: K split hi/lo bf16; V single fp16
        #pragma unroll
        for (int t = 0; t < 4; t++) {
            int f = tid + t * 256;
            int row = f >> 4;
            int c4 = (f & 15) << 2;
            size_t rb = ((size_t)(b * N_ + j0 + row)) * QKVD + h * DH + c4;
            float4 kv = *(const float4*)&g_qkv[rb + DM];
            split_store(Kh + row * LQ + c4, Kl + row * LQ + c4, kv);
            float4 vv = *(const float4*)&g_qkv[rb + 2 * DM];
            cvt_store_h16(Vh + row * LQ + c4, vv);
        }
        if (tid < 64)
            madd[tid] = mask[(size_t)b * N_ + j0 + tid] ? -1e30f : 0.0f;
        __syncthreads();

        // prefetch bias tile into registers (overlaps the S-MMA block)
        const float* bp0 = &g_bias[bias_row0 + j0];
        const float* bp1 = bp0 + 8 * N_;
        float2 bz0r[8], bz1r[8];
        #pragma unroll
        for (int nt = 0; nt < 8; nt++) {
            int col = 8 * nt + tg * 2;
            bz0r[nt] = *(const float2*)&bp0[col];
            bz1r[nt] = *(const float2*)&bp1[col];
        }

        float sacc[8][4];
        #pragma unroll
        for (int nt = 0; nt < 8; nt++)
            #pragma unroll
            for (int r = 0; r < 4; r++) sacc[nt][r] = 0.f;

        #pragma unroll
        for (int kc = 0; kc < 4; kc++) {
            int qb = qrow + kc * 16;
            uint32_t qh[4], ql[4];
            qh[0] = *(const uint32_t*)(Qh + qb);
            qh[1] = *(const uint32_t*)(Qh + qb + 8 * LQ);
            qh[2] = *(const uint32_t*)(Qh + qb + 8);
            qh[3] = *(const uint32_t*)(Qh + qb + 8 * LQ + 8);
            ql[0] = *(const uint32_t*)(Ql + qb);
            ql[1] = *(const uint32_t*)(Ql + qb + 8 * LQ);
            ql[2] = *(const uint32_t*)(Ql + qb + 8);
            ql[3] = *(const uint32_t*)(Ql + qb + 8 * LQ + 8);
            #pragma unroll
            for (int nt = 0; nt < 8; nt++) {
                int kb = (8 * nt + g) * LQ + kc * 16 + tg * 2;
                uint32_t bh[2], bl[2];
                bh[0] = *(const uint32_t*)(Kh + kb);
                bh[1] = *(const uint32_t*)(Kh + kb + 8);
                bl[0] = *(const uint32_t*)(Kl + kb);
                bl[1] = *(const uint32_t*)(Kl + kb + 8);
                MMA16816(sacc[nt], qh, bh);
                MMA16816(sacc[nt], ql, bh);
                MMA16816(sacc[nt], qh, bl);
            }
        }

        // logits (base-2): S*(scale*log2e) + prefetched bias + mask
        #pragma unroll
        for (int nt = 0; nt < 8; nt++) {
            int col = 8 * nt + tg * 2;
            float2 mz = *(float2*)&madd[col];
            sacc[nt][0] = fmaf(sacc[nt][0], SCALE_L2E, bz0r[nt].x) + mz.x;
            sacc[nt][1] = fmaf(sacc[nt][1], SCALE_L2E, bz0r[nt].y) + mz.y;
            sacc[nt][2] = fmaf(sacc[nt][2], SCALE_L2E, bz1r[nt].x) + mz.x;
            sacc[nt][3] = fmaf(sacc[nt][3], SCALE_L2E, bz1r[nt].y) + mz.y;
        }

        float mx0 = -INFINITY, mx1 = -INFINITY;
        #pragma unroll
        for (int nt = 0; nt < 8; nt++) {
            mx0 = fmaxf(mx0, fmaxf(sacc[nt][0], sacc[nt][1]));
            mx1 = fmaxf(mx1, fmaxf(sacc[nt][2], sacc[nt][3]));
        }
        mx0 = fmaxf(mx0, __shfl_xor_sync(0xffffffffu, mx0, 1));
        mx0 = fmaxf(mx0, __shfl_xor_sync(0xffffffffu, mx0, 2));
        mx1 = fmaxf(mx1, __shfl_xor_sync(0xffffffffu, mx1, 1));
        mx1 = fmaxf(mx1, __shfl_xor_sync(0xffffffffu, mx1, 2));

        float mn0 = fmaxf(m0r, mx0), mn1 = fmaxf(m1r, mx1);
        float a0 = ex2f(m0r - mn0), a1 = ex2f(m1r - mn1);
        m0r = mn0; m1r = mn1;

        float rs0 = 0.f, rs1 = 0.f;
        #pragma unroll
        for (int nt = 0; nt < 8; nt++) {
            float p0 = ex2f(sacc[nt][0] - mn0);
            float p1 = ex2f(sacc[nt][1] - mn0);
            float p2 = ex2f(sacc[nt][2] - mn1);
            float p3 = ex2f(sacc[nt][3] - mn1);
            sacc[nt][0] = p0; sacc[nt][1] = p1;
            sacc[nt][2] = p2; sacc[nt][3] = p3;
            rs0 += p0 + p1; rs1 += p2 + p3;
        }
        rs0 += __shfl_xor_sync(0xffffffffu, rs0, 1);
        rs0 += __shfl_xor_sync(0xffffffffu, rs0, 2);
        rs1 += __shfl_xor_sync(0xffffffffu, rs1, 1);
        rs1 += __shfl_xor_sync(0xffffffffu, rs1, 2);
        l0r = l0r * a0 + rs0;
        l1r = l1r * a1 + rs1;
        #pragma unroll
        for (int nt = 0; nt < 8; nt++) {
            oacc[nt][0] *= a0; oacc[nt][1] *= a0;
            oacc[nt][2] *= a1; oacc[nt][3] *= a1;
        }

        // O += P V : fp16 2-pass (P hi + P lo, V single fp16)
        #pragma unroll
        for (int kc = 0; kc < 4; kc++) {
            uint32_t ph[4], pl[4];
            split2h(sacc[2 * kc][0],     sacc[2 * kc][1],     ph[0], pl[0]);
            split2h(sacc[2 * kc][2],     sacc[2 * kc][3],     ph[1], pl[1]);
            split2h(sacc[2 * kc + 1][0], sacc[2 * kc + 1][1], ph[2], pl[2]);
            split2h(sacc[2 * kc + 1][2], sacc[2 * kc + 1][3], ph[3], pl[3]);

            uint32_t rowoff = (uint32_t)((16 * kc + (lane & 15)) * LQ) * 2;
            #pragma unroll
            for (int ntd = 0; ntd < 8; ntd++) {
                uint32_t bh[2];
                LDMX2T(bh[0], bh[1], vh_u32 + rowoff + ntd * 16);
                MMA16816H(oacc[ntd], ph, bh);
                MMA16816H(oacc[ntd], pl, bh);
            }
        }
    }

    float inv0 = 1.0f / l0r, inv1 = 1.0f / l1r;
    const size_t orow0 = ((size_t)(b * N_ + i0 + w * 16 + g)) * DM + h * DH;
    const size_t orow1 = orow0 + (size_t)8 * DM;
    #pragma unroll
    for (int nt = 0; nt < 8; nt++) {
        int col = 8 * nt + tg * 2;
        *(float2*)&g_att[orow0 + col] =
            make_float2(oacc[nt][0] * inv0, oacc[nt][1] * inv0);
        *(float2*)&g_att[orow1 + col] =
            make_float2(oacc[nt][2] * inv1, oacc[nt][3] * inv1);
    }
}

// =====================================================================
extern "C" void kernel_launch(void* const* d_in, const int* in_sizes, int n_in,
                              void* d_out, int out_size)
{
    const float* x        = (const float*)d_in[0];
    const float* coords   = (const float*)d_in[1];
    const unsigned char* mask = (const unsigned char*)d_in[2];
    const float* qkv_w    = (const float*)d_in[3];
    const float* out_w    = (const float*)d_in[4];
    const float* out_b    = (const float*)d_in[5];
    const float* alpha    = (const float*)d_in[6];
    const float* w1       = (const float*)d_in[7];
    const float* b1       = (const float*)d_in[8];
    const float* w2       = (const float*)d_in[9];
    const float* b2       = (const float*)d_in[10];
    const float* cscales  = (const float*)d_in[11];
    float* out            = (float*)d_out;

    cudaFuncSetAttribute(k_gemm_qkv_mma, cudaFuncAttributeMaxDynamicSharedMemorySize,
                         GEMM_SMEM);
    cudaFuncSetAttribute(k_gemm_out_mma, cudaFuncAttributeMaxDynamicSharedMemorySize,
                         GEMM_SMEM);
    cudaFuncSetAttribute(k_attn_mma, cudaFuncAttributeMaxDynamicSharedMemorySize,
                         ATTN_SMEM2);

    // QKV projection (mma.sync split-bf16)
    {
        dim3 grid(QKVD / 128, (B_ * N_) / 128);
        k_gemm_qkv_mma<<<grid, 256, GEMM_SMEM>>>(x, qkv_w);
    }
    // pairwise bias MLP (tensorized; bias pre-scaled by alpha*log2e)
    {
        dim3 grid(N_ / 128, N_ / 8, B_);
        k_bias_mma<<<grid, 256>>>(coords, cscales, w1, b1, w2, b2, alpha);
    }
    // tensor-core flash attention (fp16 2-pass PV)
    {
        dim3 grid(N_ / 128, H_, B_);
        k_attn_mma<<<grid, 256, ATTN_SMEM2>>>(mask);
    }
    // output projection
    {
        dim3 grid(DM / 128, (B_ * N_) / 128);
        k_gemm_out_mma<<<grid, 256, GEMM_SMEM>>>(out_w, out_b, out);
    }
}

// round 17
// speedup vs baseline: 1.7158x; 1.0377x over previous
#include <cuda_runtime.h>
#include <cuda_bf16.h>
#include <cuda_fp16.h>
#include <cstdint>
#include <math.h>

#define B_   8
#define N_   1024
#define DM   512
#define H_   8
#define DH   64
#define QKVD 1536
#define NS_  1
#define L2E_ 1.4426950408889634f
#define SCALE_L2E (0.125f * L2E_)   // attn scale folded with log2(e)

// ---------------- scratch (device globals; no allocations) ----------------
__device__ float g_qkv[(size_t)B_ * N_ * QKVD];        //  50.3 MB  [b][n][3D]
__device__ float g_bias[(size_t)B_ * H_ * N_ * N_];    // 268.4 MB  pre-scaled by alpha*log2e
__device__ float g_att[(size_t)B_ * N_ * DM];          //  16.8 MB  [b][n][h*64+d]

// =====================================================================
// common helpers
// =====================================================================
#define MMA16816(d, a, b) \
  asm volatile("mma.sync.aligned.m16n8k16.row.col.f32.bf16.bf16.f32 " \
    "{%0,%1,%2,%3}, {%4,%5,%6,%7}, {%8,%9}, {%0,%1,%2,%3};" \
    : "+f"((d)[0]), "+f"((d)[1]), "+f"((d)[2]), "+f"((d)[3]) \
    : "r"((a)[0]), "r"((a)[1]), "r"((a)[2]), "r"((a)[3]), \
      "r"((b)[0]), "r"((b)[1]))

// k8 variant: K=8 — A frag {a0=row g, a1=row g+8}, B frag {b0}. Used for
// the bias layer1 whose real K is 4 (upper K-half registers were all-zero).
#define MMA16808(d, a0, a1, b0) \
  asm volatile("mma.sync.aligned.m16n8k8.row.col.f32.bf16.bf16.f32 " \
    "{%0,%1,%2,%3}, {%4,%5}, {%6}, {%0,%1,%2,%3};" \
    : "+f"((d)[0]), "+f"((d)[1]), "+f"((d)[2]), "+f"((d)[3]) \
    : "r"(a0), "r"(a1), "r"(b0))

// fp16 variant (same shape/throughput; used for PV where fp16's 11-bit
// mantissa gives 4x finer V representation than bf16)
#define MMA16816H(d, a, b) \
  asm volatile("mma.sync.aligned.m16n8k16.row.col.f32.f16.f16.f32 " \
    "{%0,%1,%2,%3}, {%4,%5,%6,%7}, {%8,%9}, {%0,%1,%2,%3};" \
    : "+f"((d)[0]), "+f"((d)[1]), "+f"((d)[2]), "+f"((d)[3]) \
    : "r"((a)[0]), "r"((a)[1]), "r"((a)[2]), "r"((a)[3]), \
      "r"((b)[0]), "r"((b)[1]))

#define LDMX2T(r0, r1, addr) \
  asm volatile("ldmatrix.sync.aligned.m8n8.x2.trans.shared.b16 {%0,%1}, [%2];" \
    : "=r"(r0), "=r"(r1) : "r"(addr))

__device__ __forceinline__ void split2(float a, float b, uint32_t& hi, uint32_t& lo)
{
    __nv_bfloat16 ha = __float2bfloat16(a), hb = __float2bfloat16(b);
    __nv_bfloat16 la = __float2bfloat16(a - __bfloat162float(ha));
    __nv_bfloat16 lb = __float2bfloat16(b - __bfloat162float(hb));
    __nv_bfloat162 h{ha, hb}, l{la, lb};
    hi = *(uint32_t*)&h; lo = *(uint32_t*)&l;
}

// fp16 hi/lo split (for P in the PV product)
__device__ __forceinline__ void split2h(float a, float b, uint32_t& hi, uint32_t& lo)
{
    __half ha = __float2half_rn(a), hb = __float2half_rn(b);
    __half la = __float2half_rn(a - __half2float(ha));
    __half lb = __float2half_rn(b - __half2float(hb));
    __half2 h{ha, hb}, l{la, lb};
    hi = *(uint32_t*)&h; lo = *(uint32_t*)&l;
}

__device__ __forceinline__ void split_store(__nv_bfloat16* hp, __nv_bfloat16* lp,
                                            float4 v)
{
    uint32_t h0, l0, h1, l1;
    split2(v.x, v.y, h0, l0);
    split2(v.z, v.w, h1, l1);
    *(uint2*)hp = make_uint2(h0, h1);
    *(uint2*)lp = make_uint2(l0, l1);
}

// fp16 single conversion store (for V)
__device__ __forceinline__ void cvt_store_h16(__half* hp, float4 v)
{
    __half2 a{__float2half_rn(v.x), __float2half_rn(v.y)};
    __half2 b{__float2half_rn(v.z), __float2half_rn(v.w)};
    *(uint2*)hp = make_uint2(*(uint32_t*)&a, *(uint32_t*)&b);
}

// single-MUFU exp2 (softmax runs in base-2 domain)
__device__ __forceinline__ float ex2f(float x)
{
    float r;
    asm("ex2.approx.f32 %0, %1;" : "=f"(r) : "f"(x));
    return r;
}

// tanh-form GELU, single MUFU (tanh.approx): 4 FMA-class + 1 MUFU.
__device__ __forceinline__ float gelu_tanh(float t)
{
    float t2 = t * t;
    float u  = fmaf(0.0356774081f, t2, 0.7978845608f);
    float z  = t * u;
    float th;
    asm("tanh.approx.f32 %0, %1;" : "=f"(th) : "f"(z));
    float ht = 0.5f * t;
    return fmaf(ht, th, ht);
}

// =====================================================================
// mma.sync bf16 GEMM body (R5/R11-proven, unchanged)
// =====================================================================
#define KC    16
#define LDSB  24
#define PLANE (128 * LDSB)
#define STAGE (4 * PLANE)
#define GEMM_SMEM (2 * STAGE * 2)

__device__ __forceinline__ void gemm_mma_body(
    const float* __restrict__ A, const float* __restrict__ W,
    const float* __restrict__ bias, float* __restrict__ C,
    int Nc, int K, int m0, int n0)
{
    extern __shared__ __nv_bfloat16 smb[];
    const int tid  = threadIdx.x;
    const int wid  = tid >> 5, lane = tid & 31;
    const int g    = lane >> 2, tg = lane & 3;
    const int wm   = (wid >> 2) * 64,  wn = (wid & 3) * 32;

    float acc[4][4][4];
    #pragma unroll
    for (int mt = 0; mt < 4; mt++)
        #pragma unroll
        for (int nt = 0; nt < 4; nt++)
            #pragma unroll
            for (int r = 0; r < 4; r++) acc[mt][nt][r] = 0.f;

    const int NCH = K / KC;
    const int prow0 = tid >> 2;
    const int pk4   = (tid & 3) << 2;
    float4 ra[2], rw[2];

    {
        #pragma unroll
        for (int t = 0; t < 2; t++) {
            int row = prow0 + t * 64;
            ra[t] = *(const float4*)&A[(size_t)(m0 + row) * K + pk4];
            rw[t] = *(const float4*)&W[(size_t)(n0 + row) * K + pk4];
        }
        __nv_bfloat16* s = smb;
        #pragma unroll
        for (int t = 0; t < 2; t++) {
            int row = prow0 + t * 64;
            int off = row * LDSB + pk4;
            split_store(s + off,             s + PLANE + off,     ra[t]);
            split_store(s + 2 * PLANE + off, s + 3 * PLANE + off, rw[t]);
        }
    }

    for (int c = 0; c < NCH; c++) {
        __syncthreads();

        if (c + 1 < NCH) {
            const int k0 = (c + 1) * KC;
            #pragma unroll
            for (int t = 0; t < 2; t++) {
                int row = prow0 + t * 64;
                ra[t] = *(const float4*)&A[(size_t)(m0 + row) * K + k0 + pk4];
                rw[t] = *(const float4*)&W[(size_t)(n0 + row) * K + k0 + pk4];
            }
        }

        {
            const __nv_bfloat16* Ah = smb + (c & 1) * STAGE;
            const __nv_bfloat16* Al = Ah + PLANE;
            const __nv_bfloat16* Bh = Ah + 2 * PLANE;
            const __nv_bfloat16* Bl = Ah + 3 * PLANE;

            uint32_t ah[4][4], al[4][4], bh[4][2], bl[4][2];
            #pragma unroll
            for (int mt = 0; mt < 4; mt++) {
                int base = (wm + mt * 16 + g) * LDSB + tg * 2;
                ah[mt][0] = *(const uint32_t*)(Ah + base);
                ah[mt][1] = *(const uint32_t*)(Ah + base + 8 * LDSB);
                ah[mt][2] = *(const uint32_t*)(Ah + base + 8);
                ah[mt][3] = *(const uint32_t*)(Ah + base + 8 * LDSB + 8);
                al[mt][0] = *(const uint32_t*)(Al + base);
                al[mt][1] = *(const uint32_t*)(Al + base + 8 * LDSB);
                al[mt][2] = *(const uint32_t*)(Al + base + 8);
                al[mt][3] = *(const uint32_t*)(Al + base + 8 * LDSB + 8);
            }
            #pragma unroll
            for (int nt = 0; nt < 4; nt++) {
                int base = (wn + nt * 8 + g) * LDSB + tg * 2;
                bh[nt][0] = *(const uint32_t*)(Bh + base);
                bh[nt][1] = *(const uint32_t*)(Bh + base + 8);
                bl[nt][0] = *(const uint32_t*)(Bl + base);
                bl[nt][1] = *(const uint32_t*)(Bl + base + 8);
            }
            #pragma unroll
            for (int mt = 0; mt < 4; mt++)
                #pragma unroll
                for (int nt = 0; nt < 4; nt++)
                    MMA16816(acc[mt][nt], ah[mt], bh[nt]);
            #pragma unroll
            for (int mt = 0; mt < 4; mt++)
                #pragma unroll
                for (int nt = 0; nt < 4; nt++)
                    MMA16816(acc[mt][nt], al[mt], bh[nt]);
            #pragma unroll
            for (int mt = 0; mt < 4; mt++)
                #pragma unroll
                for (int nt = 0; nt < 4; nt++)
                    MMA16816(acc[mt][nt], ah[mt], bl[nt]);
        }

        if (c + 1 < NCH) {
            __nv_bfloat16* s = smb + ((c + 1) & 1) * STAGE;
            #pragma unroll
            for (int t = 0; t < 2; t++) {
                int row = prow0 + t * 64;
                int off = row * LDSB + pk4;
                split_store(s + off,             s + PLANE + off,     ra[t]);
                split_store(s + 2 * PLANE + off, s + 3 * PLANE + off, rw[t]);
            }
        }
    }

    #pragma unroll
    for (int mt = 0; mt < 4; mt++) {
        #pragma unroll
        for (int nt = 0; nt < 4; nt++) {
            int row = m0 + wm + mt * 16 + g;
            int col = n0 + wn + nt * 8 + tg * 2;
            float bx = 0.f, by = 0.f;
            if (bias) { bx = bias[col]; by = bias[col + 1]; }
            *(float2*)&C[(size_t)row * Nc + col] =
                make_float2(acc[mt][nt][0] + bx, acc[mt][nt][1] + by);
            *(float2*)&C[(size_t)(row + 8) * Nc + col] =
                make_float2(acc[mt][nt][2] + bx, acc[mt][nt][3] + by);
        }
    }
}

__global__ void __launch_bounds__(256, 2)
k_gemm_qkv_mma(const float* __restrict__ x, const float* __restrict__ qkv_w)
{
    gemm_mma_body(x, qkv_w, nullptr, g_qkv, QKVD, DM,
                  blockIdx.y * 128, blockIdx.x * 128);
}

__global__ void __launch_bounds__(256, 2)
k_gemm_out_mma(const float* __restrict__ out_w, const float* __restrict__ out_b,
               float* __restrict__ out)
{
    gemm_mma_body(g_att, out_w, out_b, out, DM, DM,
                  blockIdx.y * 128, blockIdx.x * 128);
}

// =====================================================================
// Pairwise bias MLP — tensorized; layer1 now uses m16n8k8 (real K=4,
// padded to 8 instead of 16: dropped halves were exactly zero, so
// results are bit-identical with half the layer1 tensor occupancy).
// Bias stored pre-scaled by alpha*log2(e) for the base-2 softmax.
// =====================================================================
__global__ void __launch_bounds__(256)
k_bias_mma(const float* __restrict__ coords, const float* __restrict__ cs,
           const float* __restrict__ w1, const float* __restrict__ b1,
           const float* __restrict__ w2, const float* __restrict__ b2,
           const float* __restrict__ alpha_p)
{
    __shared__ float sj[128 * 3];
    __shared__ float sci[8 * 3];
    __shared__ float sw1[128];
    __shared__ float sb1[32];
    __shared__ float sw2[256];
    __shared__ float sb2[8];
    __shared__ float sinv[3];
    __shared__ float salpha;

    const int tid = threadIdx.x;
    const int w = tid >> 5, lane = tid & 31;
    const int g = lane >> 2, tg = lane & 3;
    const int b = blockIdx.z;
    const int j0 = blockIdx.x * 128;
    const int i0 = blockIdx.y * 8;

    if (tid < 3) sinv[tid] = 1.0f / cs[tid];
    if (tid < 128) sw1[tid] = w1[tid];
    if (tid >= 128 && tid < 160) sb1[tid - 128] = b1[tid - 128];
    if (tid >= 160 && tid < 168) sb2[tid - 160] = b2[tid - 160];
    if (tid == 168) salpha = alpha_p[0] * L2E_;
    __syncthreads();
    for (int idx = tid; idx < 384; idx += 256) {
        int r = idx / 3, c = idx - r * 3;
        sj[idx] = coords[((size_t)(b * N_ + j0 + r)) * 3 + c] * sinv[c];
    }
    if (tid < 24) {
        int r = tid / 3, c = tid - r * 3;
        sci[tid] = coords[((size_t)(b * N_ + i0 + r)) * 3 + c] * sinv[c];
    }
    if (tid < 256) sw2[tid] = w2[tid];
    __syncthreads();

    // layer1 B-fragments for k8: single reg per n-tile (K rows 0..7,
    // only k<4 nonzero)
    uint32_t bw1h[4], bw1l[4];
    #pragma unroll
    for (int nt = 0; nt < 4; nt++) {
        float x0 = 0.f, x1 = 0.f;
        if (tg < 2) {
            x0 = sw1[(nt * 8 + g) * 4 + 2 * tg];
            x1 = sw1[(nt * 8 + g) * 4 + 2 * tg + 1];
        }
        split2(x0, x1, bw1h[nt], bw1l[nt]);
    }
    uint32_t bw2h[2][2], bw2l[2][2];
    #pragma unroll
    for (int kc = 0; kc < 2; kc++) {
        split2(sw2[g * 32 + 16 * kc + 2 * tg],
               sw2[g * 32 + 16 * kc + 2 * tg + 1], bw2h[kc][0], bw2l[kc][0]);
        split2(sw2[g * 32 + 16 * kc + 2 * tg + 8],
               sw2[g * 32 + 16 * kc + 2 * tg + 9], bw2h[kc][1], bw2l[kc][1]);
    }

    const int jlA = w * 16 + g;
    const int jlB = jlA + 8;
    const float cjAx = sj[jlA * 3], cjAy = sj[jlA * 3 + 1], cjAz = sj[jlA * 3 + 2];
    const float cjBx = sj[jlB * 3], cjBy = sj[jlB * 3 + 1], cjBz = sj[jlB * 3 + 2];
    const int jA = j0 + jlA, jB = j0 + jlB;
    const int h0 = 2 * tg, h1 = h0 + 1;
    const float bh0 = sb2[h0], bh1 = sb2[h1];

    #pragma unroll
    for (int ii = 0; ii < 8; ii++) {
        const int i = i0 + ii;
        const float cix = sci[ii * 3], ciy = sci[ii * 3 + 1], ciz = sci[ii * 3 + 2];

        float dxA = cix - cjAx, dyA = ciy - cjAy, dzA = ciz - cjAz;
        float dsA = sqrtf(fmaf(dxA, dxA, fmaf(dyA, dyA, dzA * dzA)));
        float dxB = cix - cjBx, dyB = ciy - cjBy, dzB = ciz - cjBz;
        float dsB = sqrtf(fmaf(dxB, dxB, fmaf(dyB, dyB, dzB * dzB)));

        // A fragments for k8: a0 = pair row g (k=2tg..2tg+1), a1 = row g+8
        float vA0 = tg == 0 ? dxA : (tg == 1 ? dzA : 0.f);
        float vA1 = tg == 0 ? dyA : (tg == 1 ? dsA : 0.f);
        float vB0 = tg == 0 ? dxB : (tg == 1 ? dzB : 0.f);
        float vB1 = tg == 0 ? dyB : (tg == 1 ? dsB : 0.f);
        uint32_t a0h, a0l, a1h, a1l;
        split2(vA0, vA1, a0h, a0l);
        split2(vB0, vB1, a1h, a1l);

        // layer1 (4 n-tiles x 3 passes, k8)
        float d1[4][4];
        #pragma unroll
        for (int nt = 0; nt < 4; nt++) {
            d1[nt][0] = d1[nt][1] = d1[nt][2] = d1[nt][3] = 0.f;
            MMA16808(d1[nt], a0h, a1h, bw1h[nt]);
            MMA16808(d1[nt], a0l, a1l, bw1h[nt]);
            MMA16808(d1[nt], a0h, a1h, bw1l[nt]);
        }

        float gv[4][4];
        #pragma unroll
        for (int nt = 0; nt < 4; nt++) {
            float ba = sb1[8 * nt + 2 * tg], bb = sb1[8 * nt + 2 * tg + 1];
            gv[nt][0] = gelu_tanh(d1[nt][0] + ba);
            gv[nt][1] = gelu_tanh(d1[nt][1] + bb);
            gv[nt][2] = gelu_tanh(d1[nt][2] + ba);
            gv[nt][3] = gelu_tanh(d1[nt][3] + bb);
        }

        float d2[4] = {0.f, 0.f, 0.f, 0.f};
        #pragma unroll
        for (int kc = 0; kc < 2; kc++) {
            uint32_t a2h[4], a2l[4];
            split2(gv[2 * kc][0],     gv[2 * kc][1],     a2h[0], a2l[0]);
            split2(gv[2 * kc][2],     gv[2 * kc][3],     a2h[1], a2l[1]);
            split2(gv[2 * kc + 1][0], gv[2 * kc + 1][1], a2h[2], a2l[2]);
            split2(gv[2 * kc + 1][2], gv[2 * kc + 1][3], a2h[3], a2l[3]);
            MMA16816(d2, a2h, bw2h[kc]);
            MMA16816(d2, a2l, bw2h[kc]);
            MMA16816(d2, a2h, bw2l[kc]);
        }

        float si = (i >= NS_) ? salpha : 0.f;
        float sA = (jA >= NS_) ? si : 0.f;
        float sB = si;
        size_t r0 = ((size_t)(b * H_ + h0) * N_ + i) * N_;
        size_t r1 = ((size_t)(b * H_ + h1) * N_ + i) * N_;
        g_bias[r0 + jA] = sA * (d2[0] + bh0);
        g_bias[r1 + jA] = sA * (d2[1] + bh1);
        g_bias[r0 + jB] = sB * (d2[2] + bh0);
        g_bias[r1 + jB] = sB * (d2[3] + bh1);
    }
}

// =====================================================================
// Tensor-core flash attention (R16-proven, unchanged): base-2 softmax,
// 2 CTAs/SM, bias prefetch, S bf16 3-pass, PV fp16 2-pass.
// =====================================================================
#define LQ 72
#define ATTN_SMEM2 (32256 * 2 + 64 * 4)

__global__ void __launch_bounds__(256, 2)
k_attn_mma(const unsigned char* __restrict__ mask)
{
    extern __shared__ __nv_bfloat16 sma[];
    __nv_bfloat16* Qh = sma;
    __nv_bfloat16* Ql = sma + 9216;
    __nv_bfloat16* Kh = sma + 18432;
    __nv_bfloat16* Kl = sma + 23040;
    __half*        Vh = (__half*)(sma + 27648);
    float* madd = (float*)(sma + 32256);

    const int b = blockIdx.z, h = blockIdx.y;
    const int i0 = blockIdx.x * 128;
    const int tid = threadIdx.x;
    const int w = tid >> 5, lane = tid & 31;
    const int g = lane >> 2, tg = lane & 3;

    const uint32_t vh_u32 = (uint32_t)__cvta_generic_to_shared(Vh);

    #pragma unroll
    for (int t = 0; t < 8; t++) {
        int f = tid + t * 256;
        int row = f >> 4;
        int c4 = (f & 15) << 2;
        float4 v = *(const float4*)&g_qkv[((size_t)(b * N_ + i0 + row)) * QKVD + h * DH + c4];
        split_store(Qh + row * LQ + c4, Ql + row * LQ + c4, v);
    }

    float oacc[8][4];
    #pragma unroll
    for (int nt = 0; nt < 8; nt++)
        #pragma unroll
        for (int r = 0; r < 4; r++) oacc[nt][r] = 0.f;
    float m0r = -INFINITY, m1r = -INFINITY, l0r = 0.f, l1r = 0.f;

    const size_t bias_row0 = ((size_t)(b * H_ + h) * N_ + (i0 + w * 16 + g)) * N_;
    const int qrow = (w * 16 + g) * LQ + tg * 2;

    for (int j0 = 0; j0 < N_; j0 += 64) {
        __syncthreads();

        #pragma unroll
        for (int t = 0; t < 4; t++) {
            int f = tid + t * 256;
            int row = f >> 4;
            int c4 = (f & 15) << 2;
            size_t rb = ((size_t)(b * N_ + j0 + row)) * QKVD + h * DH + c4;
            float4 kv = *(const float4*)&g_qkv[rb + DM];
            split_store(Kh + row * LQ + c4, Kl + row * LQ + c4, kv);
            float4 vv = *(const float4*)&g_qkv[rb + 2 * DM];
            cvt_store_h16(Vh + row * LQ + c4, vv);
        }
        if (tid < 64)
            madd[tid] = mask[(size_t)b * N_ + j0 + tid] ? -1e30f : 0.0f;
        __syncthreads();

        const float* bp0 = &g_bias[bias_row0 + j0];
        const float* bp1 = bp0 + 8 * N_;
        float2 bz0r[8], bz1r[8];
        #pragma unroll
        for (int nt = 0; nt < 8; nt++) {
            int col = 8 * nt + tg * 2;
            bz0r[nt] = *(const float2*)&bp0[col];
            bz1r[nt] = *(const float2*)&bp1[col];
        }

        float sacc[8][4];
        #pragma unroll
        for (int nt = 0; nt < 8; nt++)
            #pragma unroll
            for (int r = 0; r < 4; r++) sacc[nt][r] = 0.f;

        #pragma unroll
        for (int kc = 0; kc < 4; kc++) {
            int qb = qrow + kc * 16;
            uint32_t qh[4], ql[4];
            qh[0] = *(const uint32_t*)(Qh + qb);
            qh[1] = *(const uint32_t*)(Qh + qb + 8 * LQ);
            qh[2] = *(const uint32_t*)(Qh + qb + 8);
            qh[3] = *(const uint32_t*)(Qh + qb + 8 * LQ + 8);
            ql[0] = *(const uint32_t*)(Ql + qb);
            ql[1] = *(const uint32_t*)(Ql + qb + 8 * LQ);
            ql[2] = *(const uint32_t*)(Ql + qb + 8);
            ql[3] = *(const uint32_t*)(Ql + qb + 8 * LQ + 8);
            #pragma unroll
            for (int nt = 0; nt < 8; nt++) {
                int kb = (8 * nt + g) * LQ + kc * 16 + tg * 2;
                uint32_t bh[2], bl[2];
                bh[0] = *(const uint32_t*)(Kh + kb);
                bh[1] = *(const uint32_t*)(Kh + kb + 8);
                bl[0] = *(const uint32_t*)(Kl + kb);
                bl[1] = *(const uint32_t*)(Kl + kb + 8);
                MMA16816(sacc[nt], qh, bh);
                MMA16816(sacc[nt], ql, bh);
                MMA16816(sacc[nt], qh, bl);
            }
        }

        #pragma unroll
        for (int nt = 0; nt < 8; nt++) {
            int col = 8 * nt + tg * 2;
            float2 mz = *(float2*)&madd[col];
            sacc[nt][0] = fmaf(sacc[nt][0], SCALE_L2E, bz0r[nt].x) + mz.x;
            sacc[nt][1] = fmaf(sacc[nt][1], SCALE_L2E, bz0r[nt].y) + mz.y;
            sacc[nt][2] = fmaf(sacc[nt][2], SCALE_L2E, bz1r[nt].x) + mz.x;
            sacc[nt][3] = fmaf(sacc[nt][3], SCALE_L2E, bz1r[nt].y) + mz.y;
        }

        float mx0 = -INFINITY, mx1 = -INFINITY;
        #pragma unroll
        for (int nt = 0; nt < 8; nt++) {
            mx0 = fmaxf(mx0, fmaxf(sacc[nt][0], sacc[nt][1]));
            mx1 = fmaxf(mx1, fmaxf(sacc[nt][2], sacc[nt][3]));
        }
        mx0 = fmaxf(mx0, __shfl_xor_sync(0xffffffffu, mx0, 1));
        mx0 = fmaxf(mx0, __shfl_xor_sync(0xffffffffu, mx0, 2));
        mx1 = fmaxf(mx1, __shfl_xor_sync(0xffffffffu, mx1, 1));
        mx1 = fmaxf(mx1, __shfl_xor_sync(0xffffffffu, mx1, 2));

        float mn0 = fmaxf(m0r, mx0), mn1 = fmaxf(m1r, mx1);
        float a0 = ex2f(m0r - mn0), a1 = ex2f(m1r - mn1);
        m0r = mn0; m1r = mn1;

        float rs0 = 0.f, rs1 = 0.f;
        #pragma unroll
        for (int nt = 0; nt < 8; nt++) {
            float p0 = ex2f(sacc[nt][0] - mn0);
            float p1 = ex2f(sacc[nt][1] - mn0);
            float p2 = ex2f(sacc[nt][2] - mn1);
            float p3 = ex2f(sacc[nt][3] - mn1);
            sacc[nt][0] = p0; sacc[nt][1] = p1;
            sacc[nt][2] = p2; sacc[nt][3] = p3;
            rs0 += p0 + p1; rs1 += p2 + p3;
        }
        rs0 += __shfl_xor_sync(0xffffffffu, rs0, 1);
        rs0 += __shfl_xor_sync(0xffffffffu, rs0, 2);
        rs1 += __shfl_xor_sync(0xffffffffu, rs1, 1);
        rs1 += __shfl_xor_sync(0xffffffffu, rs1, 2);
        l0r = l0r * a0 + rs0;
        l1r = l1r * a1 + rs1;
        #pragma unroll
        for (int nt = 0; nt < 8; nt++) {
            oacc[nt][0] *= a0; oacc[nt][1] *= a0;
            oacc[nt][2] *= a1; oacc[nt][3] *= a1;
        }

        #pragma unroll
        for (int kc = 0; kc < 4; kc++) {
            uint32_t ph[4], pl[4];
            split2h(sacc[2 * kc][0],     sacc[2 * kc][1],     ph[0], pl[0]);
            split2h(sacc[2 * kc][2],     sacc[2 * kc][3],     ph[1], pl[1]);
            split2h(sacc[2 * kc + 1][0], sacc[2 * kc + 1][1], ph[2], pl[2]);
            split2h(sacc[2 * kc + 1][2], sacc[2 * kc + 1][3], ph[3], pl[3]);

            uint32_t rowoff = (uint32_t)((16 * kc + (lane & 15)) * LQ) * 2;
            #pragma unroll
            for (int ntd = 0; ntd < 8; ntd++) {
                uint32_t bh[2];
                LDMX2T(bh[0], bh[1], vh_u32 + rowoff + ntd * 16);
                MMA16816H(oacc[ntd], ph, bh);
                MMA16816H(oacc[ntd], pl, bh);
            }
        }
    }

    float inv0 = 1.0f / l0r, inv1 = 1.0f / l1r;
    const size_t orow0 = ((size_t)(b * N_ + i0 + w * 16 + g)) * DM + h * DH;
    const size_t orow1 = orow0 + (size_t)8 * DM;
    #pragma unroll
    for (int nt = 0; nt < 8; nt++) {
        int col = 8 * nt + tg * 2;
        *(float2*)&g_att[orow0 + col] =
            make_float2(oacc[nt][0] * inv0, oacc[nt][1] * inv0);
        *(float2*)&g_att[orow1 + col] =
            make_float2(oacc[nt][2] * inv1, oacc[nt][3] * inv1);
    }
}

// =====================================================================
extern "C" void kernel_launch(void* const* d_in, const int* in_sizes, int n_in,
                              void* d_out, int out_size)
{
    const float* x        = (const float*)d_in[0];
    const float* coords   = (const float*)d_in[1];
    const unsigned char* mask = (const unsigned char*)d_in[2];
    const float* qkv_w    = (const float*)d_in[3];
    const float* out_w    = (const float*)d_in[4];
    const float* out_b    = (const float*)d_in[5];
    const float* alpha    = (const float*)d_in[6];
    const float* w1       = (const float*)d_in[7];
    const float* b1       = (const float*)d_in[8];
    const float* w2       = (const float*)d_in[9];
    const float* b2       = (const float*)d_in[10];
    const float* cscales  = (const float*)d_in[11];
    float* out            = (float*)d_out;

    cudaFuncSetAttribute(k_gemm_qkv_mma, cudaFuncAttributeMaxDynamicSharedMemorySize,
                         GEMM_SMEM);
    cudaFuncSetAttribute(k_gemm_out_mma, cudaFuncAttributeMaxDynamicSharedMemorySize,
                         GEMM_SMEM);
    cudaFuncSetAttribute(k_attn_mma, cudaFuncAttributeMaxDynamicSharedMemorySize,
                         ATTN_SMEM2);

    // QKV projection (mma.sync split-bf16)
    {
        dim3 grid(QKVD / 128, (B_ * N_) / 128);
        k_gemm_qkv_mma<<<grid, 256, GEMM_SMEM>>>(x, qkv_w);
    }
    // pairwise bias MLP (tensorized; layer1 on k8 MMAs)
    {
        dim3 grid(N_ / 128, N_ / 8, B_);
        k_bias_mma<<<grid, 256>>>(coords, cscales, w1, b1, w2, b2, alpha);
    }
    // tensor-core flash attention (fp16 2-pass PV)
    {
        dim3 grid(N_ / 128, H_, B_);
        k_attn_mma<<<grid, 256, ATTN_SMEM2>>>(mask);
    }
    // output projection
    {
        dim3 grid(DM / 128, (B_ * N_) / 128);
        k_gemm_out_mma<<<grid, 256, GEMM_SMEM>>>(out_w, out_b, out);
    }
}